// round 11
// baseline (speedup 1.0000x reference)
#include <cuda_runtime.h>
#include <cuda_fp16.h>
#include <cstdint>
#include <cstddef>
#include <math.h>

#define BNUM 16
#define HW   1024
#define C    512
#define G    32
#define CG   16
#define NQKV 1536
#define MTOT (BNUM * HW)
#define SCALE 0.044194173824159216f   // 512^-0.5
#define NPERS 148                     // persistent CTAs (1/SM, conservative SM count)

// fp16 scratch
__device__ __half g_xh[MTOT * C];
__device__ __half g_qh[MTOT * C];
__device__ __half g_kh[MTOT * C];
__device__ __half g_vh[MTOT * C];
__device__ __half g_sh[(size_t)BNUM * HW * HW];
__device__ __half g_oh[MTOT * C];
__device__ __half g_wqkvh[NQKV * C];   // permuted: [n'=e*512+ch][k], q-scale folded
__device__ __half g_wouth[C * C];
__device__ float  g_bqr[NQKV];         // permuted (scaled) qkv bias

// ---------------------------------------------------------------------------
// helpers
// ---------------------------------------------------------------------------
__device__ __forceinline__ uint32_t smaddr(const void* p) {
    return (uint32_t)__cvta_generic_to_shared(p);
}
__device__ __forceinline__ uint32_t swz(uint32_t off) {       // SW128 for 128B rows
    return off ^ ((off >> 3) & 0x70);
}
__device__ __forceinline__ void ldsm4(uint32_t a, uint32_t& r0, uint32_t& r1,
                                      uint32_t& r2, uint32_t& r3) {
    asm volatile("ldmatrix.sync.aligned.m8n8.x4.shared.b16 {%0,%1,%2,%3},[%4];"
                 : "=r"(r0), "=r"(r1), "=r"(r2), "=r"(r3) : "r"(a));
}
__device__ __forceinline__ void ldsm4t(uint32_t a, uint32_t& r0, uint32_t& r1,
                                       uint32_t& r2, uint32_t& r3) {
    asm volatile("ldmatrix.sync.aligned.m8n8.x4.trans.shared.b16 {%0,%1,%2,%3},[%4];"
                 : "=r"(r0), "=r"(r1), "=r"(r2), "=r"(r3) : "r"(a));
}
__device__ __forceinline__ void mma16816(float* d, const uint32_t* a, const uint32_t* b) {
    asm volatile(
        "mma.sync.aligned.m16n8k16.row.col.f32.f16.f16.f32 "
        "{%0,%1,%2,%3},{%4,%5,%6,%7},{%8,%9},{%0,%1,%2,%3};"
        : "+f"(d[0]), "+f"(d[1]), "+f"(d[2]), "+f"(d[3])
        : "r"(a[0]), "r"(a[1]), "r"(a[2]), "r"(a[3]), "r"(b[0]), "r"(b[1]));
}
#define CPA16(dst, src) \
    asm volatile("cp.async.cg.shared.global [%0],[%1],16;" ::"r"(dst), "l"(src))
#define CPCOMMIT() asm volatile("cp.async.commit_group;")
#define CPWAIT0()  asm volatile("cp.async.wait_group 0;")
#define CPWAIT1()  asm volatile("cp.async.wait_group 1;")

// ---------------------------------------------------------------------------
// weight converters (QKV permuted to [n'][k] + scale/bias folded)
// ---------------------------------------------------------------------------
__global__ void conv_wqkv(const float* __restrict__ W, const float* __restrict__ bq) {
    int idx = blockIdx.x * 256 + threadIdx.x;
    if (idx >= NQKV * C) return;
    int np = idx >> 9;          // n' = e*512 + ch
    int k  = idx & 511;
    int e  = np >> 9;
    int ch = np & 511;
    float s = (e == 0) ? SCALE : 1.0f;
    g_wqkvh[idx] = __float2half_rn(W[(size_t)k * NQKV + ch * 3 + e] * s);
    if (k == 0) g_bqr[np] = bq[ch * 3 + e] * s;
}
__global__ void f2h_wout(const float* __restrict__ s) {
    int i = blockIdx.x * 256 + threadIdx.x;
    if (i < C * C) g_wouth[i] = __float2half_rn(s[i]);
}

// ---------------------------------------------------------------------------
// GroupNorm -> fp16 g_xh (shuffle reduction, float2/half2)
// ---------------------------------------------------------------------------
__global__ void groupnorm_kernel(const float* __restrict__ in,
                                 const float* __restrict__ gamma,
                                 const float* __restrict__ beta) {
    int b = blockIdx.x >> 5;
    int g = blockIdx.x & 31;
    int tid = threadIdx.x, lane = tid & 31, warp = tid >> 5;
    const float* base = in + (size_t)b * HW * C + g * CG;
    float s = 0.f, ss = 0.f;
    for (int e = tid; e < HW * 8; e += 256) {       // float2 granules
        int pos = e >> 3, c2 = e & 7;
        float2 v = *(const float2*)(base + (size_t)pos * C + c2 * 2);
        s += v.x + v.y; ss += v.x * v.x + v.y * v.y;
    }
#pragma unroll
    for (int o = 16; o; o >>= 1) {
        s  += __shfl_xor_sync(0xffffffffu, s, o);
        ss += __shfl_xor_sync(0xffffffffu, ss, o);
    }
    __shared__ float sm_s[8], sm_ss[8];
    if (lane == 0) { sm_s[warp] = s; sm_ss[warp] = ss; }
    __syncthreads();
    float ts = 0.f, tss = 0.f;
#pragma unroll
    for (int i = 0; i < 8; i++) { ts += sm_s[i]; tss += sm_ss[i]; }
    const float invN = 1.0f / (HW * CG);
    float mean = ts * invN;
    float var  = tss * invN - mean * mean;
    float rstd = rsqrtf(var + 1e-3f);
    __half* outb = g_xh + (size_t)b * HW * C + g * CG;
    for (int e = tid; e < HW * 8; e += 256) {
        int pos = e >> 3, c2 = e & 7;
        float2 v = *(const float2*)(base + (size_t)pos * C + c2 * 2);
        float g0 = gamma[g * CG + c2 * 2], g1 = gamma[g * CG + c2 * 2 + 1];
        float b0 = beta[g * CG + c2 * 2],  b1 = beta[g * CG + c2 * 2 + 1];
        *(__half2*)(outb + (size_t)pos * C + c2 * 2) =
            __floats2half2_rn((v.x - mean) * rstd * g0 + b0,
                              (v.y - mean) * rstd * g1 + b1);
    }
}

// ---------------------------------------------------------------------------
// Persistent fp16 mma.sync GEMM: 256 thr (4x2 warps, 64x64 warp tile),
// block tile 256x128 (MxN), BK=64, 3-stage cp.async (distance 2),
// 1 barrier/step, frag ping-pong, SW128 swizzle, 1 CTA/SM.
// Rationale: 256x128 halves smem traffic per MAC (smem port was co-saturating
// with the tensor pipe at 128x128).
// ---------------------------------------------------------------------------
template <int EPI>
__global__ void __launch_bounds__(256, 1)
gemm_mma(const float* __restrict__ bias,
         const float* __restrict__ resid,
         float* __restrict__ outF) {
    constexpr bool NT  = (EPI <= 1);
    constexpr int  K   = (EPI == 2) ? 1024 : 512;
    constexpr int  KT  = K / 64;
    constexpr int  LDA = (EPI == 2) ? 1024 : 512;
    constexpr int  LDB = 512;
    constexpr int  TX  = (EPI == 0) ? 12 : ((EPI == 1) ? 8 : 4);
    constexpr int  TY  = (EPI == 1 || EPI == 2) ? 4 : 64;     // M tiles of 256
    constexpr int  TZ  = (EPI == 1 || EPI == 2) ? 16 : 1;
    constexpr int  T   = TX * TY * TZ;

    constexpr int ASTG_B = 256 * 128;                          // 32 KB
    constexpr int BSTG_B = NT ? (128 * 128) : (64 * 272);      // 16 KB / 17 KB
    extern __shared__ char smc[];
    char* Abuf = smc;
    char* Bbuf = smc + 3 * ASTG_B;

    int tid = threadIdx.x, lane = tid & 31, warp = tid >> 5;
    int wm = warp & 3, wn = warp >> 2;            // 4x2 warp grid, 64x64 tiles
    int bid = blockIdx.x;
    int GP = gridDim.x;
    int myN = (bid < T) ? ((T - 1 - bid) / GP + 1) : 0;
    int S = myN * KT;

    float acc[4][8][4] = {};

    auto tileinfo = [&](int i, int& m0, int& n0, int& z) {
        int t = bid + i * GP;
        int x = t % TX;
        int y = (t / TX) % TY;
        z = t / (TX * TY);
        m0 = y * 256; n0 = x * 128;
    };

    auto load = [&](int s) {
        int i = s / KT;
        if (i < myN) {
            int m0, n0, z;
            tileinfo(i, m0, n0, z);
            int k0 = (s % KT) * 64;
            const __half* A;
            const __half* B;
            if constexpr (EPI == 0)      { A = g_xh;                        B = g_wqkvh; }
            else if constexpr (EPI == 1) { A = g_qh + (size_t)z * HW * C;   B = g_kh + (size_t)z * HW * C; }
            else if constexpr (EPI == 2) { A = g_sh + (size_t)z * HW * HW;  B = g_vh + (size_t)z * HW * C; }
            else                         { A = g_oh;                        B = g_wouth; }
            int st = s % 3;
            uint32_t Asm = smaddr(Abuf + st * ASTG_B);
            uint32_t Bsm = smaddr(Bbuf + st * BSTG_B);
#pragma unroll
            for (int q = 0; q < 8; q++) {          // A: 256 rows x 64 halfs
                int c = tid + q * 256;
                int r = c >> 3, ch = c & 7;
                CPA16(Asm + swz((uint32_t)(r * 128 + ch * 16)),
                      A + (size_t)(m0 + r) * LDA + k0 + ch * 8);
            }
            if constexpr (NT) {
#pragma unroll
                for (int q = 0; q < 4; q++) {      // B: 128 rows(n) x 64 halfs
                    int c = tid + q * 256;
                    int r = c >> 3, ch = c & 7;
                    CPA16(Bsm + swz((uint32_t)(r * 128 + ch * 16)),
                          B + (size_t)(n0 + r) * LDB + k0 + ch * 8);
                }
            } else {
#pragma unroll
                for (int q = 0; q < 4; q++) {      // B: 64 rows(k) x 128 halfs, pad
                    int c = tid + q * 256;
                    int r = c >> 4, ch = c & 15;
                    CPA16(Bsm + (uint32_t)(r * 272 + ch * 16),
                          B + (size_t)(k0 + r) * LDB + n0 + ch * 8);
                }
            }
        }
        CPCOMMIT();
    };

    auto ldfrag = [&](int st, int ks, uint32_t a[4][4], uint32_t b[8][2]) {
        uint32_t Asm = smaddr(Abuf + st * ASTG_B);
        uint32_t Bsm = smaddr(Bbuf + st * BSTG_B);
        int colh = ks + ((lane >> 4) << 3);
#pragma unroll
        for (int mt = 0; mt < 4; mt++) {
            int r = wm * 64 + mt * 16 + (lane & 15);
            ldsm4(Asm + swz((uint32_t)(r * 128 + colh * 2)),
                  a[mt][0], a[mt][1], a[mt][2], a[mt][3]);
        }
        if constexpr (NT) {
#pragma unroll
            for (int ng = 0; ng < 4; ng++) {
                int r = wn * 64 + ng * 16 + (lane & 15);
                uint32_t r0, r1, r2, r3;
                ldsm4(Bsm + swz((uint32_t)(r * 128 + colh * 2)), r0, r1, r2, r3);
                b[2 * ng][0] = r0; b[2 * ng][1] = r2;
                b[2 * ng + 1][0] = r1; b[2 * ng + 1][1] = r3;
            }
        } else {
#pragma unroll
            for (int ng = 0; ng < 4; ng++) {
                int r = ks + (lane & 15);
                int col = wn * 64 + ng * 16 + ((lane >> 4) << 3);
                uint32_t r0, r1, r2, r3;
                ldsm4t(Bsm + (uint32_t)(r * 272 + col * 2), r0, r1, r2, r3);
                b[2 * ng][0] = r0; b[2 * ng][1] = r1;
                b[2 * ng + 1][0] = r2; b[2 * ng + 1][1] = r3;
            }
        }
    };

    auto mma_all = [&](uint32_t a[4][4], uint32_t b[8][2]) {
#pragma unroll
        for (int mt = 0; mt < 4; mt++)
#pragma unroll
            for (int nt = 0; nt < 8; nt++) mma16816(acc[mt][nt], a[mt], b[nt]);
    };

    load(0);
    load(1);

    for (int s = 0; s < S; s++) {
        if (s + 1 < S) { CPWAIT1(); } else { CPWAIT0(); }
        __syncthreads();
        load(s + 2);
        int st = s % 3;
        uint32_t a0[4][4], b0[8][2], a1[4][4], b1[8][2];
        ldfrag(st, 0,  a0, b0);
        ldfrag(st, 16, a1, b1);
        mma_all(a0, b0);
        ldfrag(st, 32, a0, b0);
        mma_all(a1, b1);
        ldfrag(st, 48, a1, b1);
        mma_all(a0, b0);
        mma_all(a1, b1);

        if ((s + 1) % KT == 0) {
            int m0, n0, z;
            tileinfo(s / KT, m0, n0, z);
#pragma unroll
            for (int mt = 0; mt < 4; mt++) {
#pragma unroll
                for (int nt = 0; nt < 8; nt++) {
                    int r  = m0 + wm * 64 + mt * 16 + (lane >> 2);
                    int nl = wn * 64 + nt * 8 + (lane & 3) * 2;
                    float* v = acc[mt][nt];
                    if constexpr (EPI == 0) {
                        int e = n0 >> 9;
                        __half* dst = (e == 0) ? g_qh : ((e == 1) ? g_kh : g_vh);
                        int ch = (n0 & 511) + nl;
                        float b0f = g_bqr[n0 + nl], b1f = g_bqr[n0 + nl + 1];
                        *(__half2*)&dst[(size_t)r * C + ch] =
                            __floats2half2_rn(v[0] + b0f, v[1] + b1f);
                        *(__half2*)&dst[(size_t)(r + 8) * C + ch] =
                            __floats2half2_rn(v[2] + b0f, v[3] + b1f);
                    } else if constexpr (EPI == 1) {
                        size_t base = (size_t)z * HW * HW;
                        int cc = n0 + nl;
                        *(__half2*)&g_sh[base + (size_t)r * HW + cc] =
                            __floats2half2_rn(v[0], v[1]);
                        *(__half2*)&g_sh[base + (size_t)(r + 8) * HW + cc] =
                            __floats2half2_rn(v[2], v[3]);
                    } else if constexpr (EPI == 2) {
                        size_t base = (size_t)z * HW * C;
                        int cc = n0 + nl;
                        *(__half2*)&g_oh[base + (size_t)r * C + cc] =
                            __floats2half2_rn(v[0], v[1]);
                        *(__half2*)&g_oh[base + (size_t)(r + 8) * C + cc] =
                            __floats2half2_rn(v[2], v[3]);
                    } else {
                        int cc = n0 + nl;
                        outF[(size_t)r * C + cc]     = v[0] + bias[cc]     + resid[(size_t)r * C + cc];
                        outF[(size_t)r * C + cc + 1] = v[1] + bias[cc + 1] + resid[(size_t)r * C + cc + 1];
                        outF[(size_t)(r + 8) * C + cc]     = v[2] + bias[cc]     + resid[(size_t)(r + 8) * C + cc];
                        outF[(size_t)(r + 8) * C + cc + 1] = v[3] + bias[cc + 1] + resid[(size_t)(r + 8) * C + cc + 1];
                    }
                }
            }
#pragma unroll
            for (int mt = 0; mt < 4; mt++)
#pragma unroll
                for (int nt = 0; nt < 8; nt++)
#pragma unroll
                    for (int j = 0; j < 4; j++) acc[mt][nt][j] = 0.f;
        }
    }
}

// ---------------------------------------------------------------------------
// fp16 in-place row softmax over 1024 cols: 128 thr, uint4/thread, 2 barriers
// ---------------------------------------------------------------------------
__global__ void softmax_h() {
    size_t row = blockIdx.x;
    uint4* p = (uint4*)(g_sh + row * HW);
    int tid = threadIdx.x, lane = tid & 31, warp = tid >> 5;
    uint4 raw = p[tid];
    __half2 h[4] = {*(__half2*)&raw.x, *(__half2*)&raw.y,
                    *(__half2*)&raw.z, *(__half2*)&raw.w};
    float2 f[4];
#pragma unroll
    for (int i = 0; i < 4; i++) f[i] = __half22float2(h[i]);

    float m = -1e30f;
#pragma unroll
    for (int i = 0; i < 4; i++) m = fmaxf(m, fmaxf(f[i].x, f[i].y));
#pragma unroll
    for (int o = 16; o; o >>= 1) m = fmaxf(m, __shfl_xor_sync(0xffffffffu, m, o));
    __shared__ float smax[4], ssum[4];
    if (lane == 0) smax[warp] = m;
    __syncthreads();
    m = fmaxf(fmaxf(smax[0], smax[1]), fmaxf(smax[2], smax[3]));

    float e[8];
    float s = 0.f;
#pragma unroll
    for (int i = 0; i < 4; i++) {
        e[2 * i]     = __expf(f[i].x - m);
        e[2 * i + 1] = __expf(f[i].y - m);
        s += e[2 * i] + e[2 * i + 1];
    }
#pragma unroll
    for (int o = 16; o; o >>= 1) s += __shfl_xor_sync(0xffffffffu, s, o);
    if (lane == 0) ssum[warp] = s;
    __syncthreads();
    float inv = 1.0f / (ssum[0] + ssum[1] + ssum[2] + ssum[3]);

    uint4 w;
    *(__half2*)&w.x = __floats2half2_rn(e[0] * inv, e[1] * inv);
    *(__half2*)&w.y = __floats2half2_rn(e[2] * inv, e[3] * inv);
    *(__half2*)&w.z = __floats2half2_rn(e[4] * inv, e[5] * inv);
    *(__half2*)&w.w = __floats2half2_rn(e[6] * inv, e[7] * inv);
    p[tid] = w;
}

// ---------------------------------------------------------------------------
extern "C" void kernel_launch(void* const* d_in, const int* in_sizes, int n_in,
                              void* d_out, int out_size) {
    (void)in_sizes; (void)n_in; (void)out_size;
    const float* inputs = (const float*)d_in[0];
    const float* gamma  = (const float*)d_in[1];
    const float* beta   = (const float*)d_in[2];
    const float* Wqkv   = (const float*)d_in[3];
    const float* bqkv   = (const float*)d_in[4];
    const float* Wout   = (const float*)d_in[5];
    const float* bout   = (const float*)d_in[6];
    float* out = (float*)d_out;

    const int smNT = 3 * (256 * 128 + 128 * 128);     // 147456
    const int smNN = 3 * (256 * 128 + 64 * 272);      // 150528
    cudaFuncSetAttribute(gemm_mma<0>, cudaFuncAttributeMaxDynamicSharedMemorySize, smNT);
    cudaFuncSetAttribute(gemm_mma<1>, cudaFuncAttributeMaxDynamicSharedMemorySize, smNT);
    cudaFuncSetAttribute(gemm_mma<2>, cudaFuncAttributeMaxDynamicSharedMemorySize, smNN);
    cudaFuncSetAttribute(gemm_mma<3>, cudaFuncAttributeMaxDynamicSharedMemorySize, smNN);

    conv_wqkv<<<(NQKV * C + 255) / 256, 256>>>(Wqkv, bqkv);
    f2h_wout<<<(C * C + 255) / 256, 256>>>(Wout);
    groupnorm_kernel<<<BNUM * G, 256>>>(inputs, gamma, beta);

    gemm_mma<0><<<NPERS, 256, smNT>>>(nullptr, nullptr, nullptr);
    gemm_mma<1><<<NPERS, 256, smNT>>>(nullptr, nullptr, nullptr);
    softmax_h<<<BNUM * HW, 128>>>();
    gemm_mma<2><<<NPERS, 256, smNN>>>(nullptr, nullptr, nullptr);
    gemm_mma<3><<<NPERS, 256, smNN>>>(bout, inputs, out);
}

// round 12
// speedup vs baseline: 1.0371x; 1.0371x over previous
#include <cuda_runtime.h>
#include <cuda_fp16.h>
#include <cstdint>
#include <cstddef>
#include <math.h>

#define BNUM 16
#define HW   1024
#define C    512
#define G    32
#define CG   16
#define NQKV 1536
#define MTOT (BNUM * HW)
#define SCALE 0.044194173824159216f   // 512^-0.5
#define NPERS 304                     // persistent CTAs (2/SM)

// fp16 scratch
__device__ __half g_xh[MTOT * C];
__device__ __half g_qh[MTOT * C];
__device__ __half g_kh[MTOT * C];
__device__ __half g_vh[MTOT * C];
__device__ __half g_sh[(size_t)BNUM * HW * HW];
__device__ __half g_oh[MTOT * C];
__device__ __half g_wqkvh[NQKV * C];   // permuted: [n'=e*512+ch][k], q-scale folded
__device__ __half g_wouth[C * C];
__device__ float  g_bqr[NQKV];         // permuted (scaled) qkv bias

// ---------------------------------------------------------------------------
// helpers
// ---------------------------------------------------------------------------
__device__ __forceinline__ uint32_t smaddr(const void* p) {
    return (uint32_t)__cvta_generic_to_shared(p);
}
__device__ __forceinline__ uint32_t swz(uint32_t off) {       // SW128 for 128B rows
    return off ^ ((off >> 3) & 0x70);
}
__device__ __forceinline__ void ldsm4(uint32_t a, uint32_t& r0, uint32_t& r1,
                                      uint32_t& r2, uint32_t& r3) {
    asm volatile("ldmatrix.sync.aligned.m8n8.x4.shared.b16 {%0,%1,%2,%3},[%4];"
                 : "=r"(r0), "=r"(r1), "=r"(r2), "=r"(r3) : "r"(a));
}
__device__ __forceinline__ void ldsm4t(uint32_t a, uint32_t& r0, uint32_t& r1,
                                       uint32_t& r2, uint32_t& r3) {
    asm volatile("ldmatrix.sync.aligned.m8n8.x4.trans.shared.b16 {%0,%1,%2,%3},[%4];"
                 : "=r"(r0), "=r"(r1), "=r"(r2), "=r"(r3) : "r"(a));
}
__device__ __forceinline__ void mma16816(float* d, const uint32_t* a, const uint32_t* b) {
    asm volatile(
        "mma.sync.aligned.m16n8k16.row.col.f32.f16.f16.f32 "
        "{%0,%1,%2,%3},{%4,%5,%6,%7},{%8,%9},{%0,%1,%2,%3};"
        : "+f"(d[0]), "+f"(d[1]), "+f"(d[2]), "+f"(d[3])
        : "r"(a[0]), "r"(a[1]), "r"(a[2]), "r"(a[3]), "r"(b[0]), "r"(b[1]));
}
#define CPA16(dst, src) \
    asm volatile("cp.async.cg.shared.global [%0],[%1],16;" ::"r"(dst), "l"(src))
#define CPCOMMIT() asm volatile("cp.async.commit_group;")
#define CPWAIT1()  asm volatile("cp.async.wait_group 1;")
#define CPWAIT2()  asm volatile("cp.async.wait_group 2;")

// ---------------------------------------------------------------------------
// weight converters (QKV permuted to [n'][k] + scale/bias folded)
// ---------------------------------------------------------------------------
__global__ void conv_wqkv(const float* __restrict__ W, const float* __restrict__ bq) {
    int idx = blockIdx.x * 256 + threadIdx.x;
    if (idx >= NQKV * C) return;
    int np = idx >> 9;          // n' = e*512 + ch
    int k  = idx & 511;
    int e  = np >> 9;
    int ch = np & 511;
    float s = (e == 0) ? SCALE : 1.0f;
    g_wqkvh[idx] = __float2half_rn(W[(size_t)k * NQKV + ch * 3 + e] * s);
    if (k == 0) g_bqr[np] = bq[ch * 3 + e] * s;
}
__global__ void f2h_wout(const float* __restrict__ s) {
    int i = blockIdx.x * 256 + threadIdx.x;
    if (i < C * C) g_wouth[i] = __float2half_rn(s[i]);
}

// ---------------------------------------------------------------------------
// GroupNorm -> fp16 g_xh (shuffle reduction, float2/half2)
// ---------------------------------------------------------------------------
__global__ void groupnorm_kernel(const float* __restrict__ in,
                                 const float* __restrict__ gamma,
                                 const float* __restrict__ beta) {
    int b = blockIdx.x >> 5;
    int g = blockIdx.x & 31;
    int tid = threadIdx.x, lane = tid & 31, warp = tid >> 5;
    const float* base = in + (size_t)b * HW * C + g * CG;
    float s = 0.f, ss = 0.f;
    for (int e = tid; e < HW * 8; e += 256) {       // float2 granules
        int pos = e >> 3, c2 = e & 7;
        float2 v = *(const float2*)(base + (size_t)pos * C + c2 * 2);
        s += v.x + v.y; ss += v.x * v.x + v.y * v.y;
    }
#pragma unroll
    for (int o = 16; o; o >>= 1) {
        s  += __shfl_xor_sync(0xffffffffu, s, o);
        ss += __shfl_xor_sync(0xffffffffu, ss, o);
    }
    __shared__ float sm_s[8], sm_ss[8];
    if (lane == 0) { sm_s[warp] = s; sm_ss[warp] = ss; }
    __syncthreads();
    float ts = 0.f, tss = 0.f;
#pragma unroll
    for (int i = 0; i < 8; i++) { ts += sm_s[i]; tss += sm_ss[i]; }
    const float invN = 1.0f / (HW * CG);
    float mean = ts * invN;
    float var  = tss * invN - mean * mean;
    float rstd = rsqrtf(var + 1e-3f);
    __half* outb = g_xh + (size_t)b * HW * C + g * CG;
    for (int e = tid; e < HW * 8; e += 256) {
        int pos = e >> 3, c2 = e & 7;
        float2 v = *(const float2*)(base + (size_t)pos * C + c2 * 2);
        float g0 = gamma[g * CG + c2 * 2], g1 = gamma[g * CG + c2 * 2 + 1];
        float b0 = beta[g * CG + c2 * 2],  b1 = beta[g * CG + c2 * 2 + 1];
        *(__half2*)(outb + (size_t)pos * C + c2 * 2) =
            __floats2half2_rn((v.x - mean) * rstd * g0 + b0,
                              (v.y - mean) * rstd * g1 + b1);
    }
}

// ---------------------------------------------------------------------------
// Persistent fp16 mma.sync GEMM: 128 thr (2x2 warps, 64x64 warp tile),
// block tile 128x128, BK=64, 3-stage cp.async, 2 CTAs/SM, NPERS CTAs.
// NEW: next-step frag prefetch — the step's first ldsm batch is issued in the
// shadow of the previous step's tail MMAs, so no ldsm latency is exposed at
// the step top. Barrier sits mid-step (still 1/step).
// ---------------------------------------------------------------------------
template <int EPI>
__global__ void __launch_bounds__(128, 2)
gemm_mma(const float* __restrict__ bias,
         const float* __restrict__ resid,
         float* __restrict__ outF) {
    constexpr bool NT  = (EPI <= 1);
    constexpr int  K   = (EPI == 2) ? 1024 : 512;
    constexpr int  KT  = K / 64;
    constexpr int  LDA = (EPI == 2) ? 1024 : 512;
    constexpr int  LDB = 512;
    constexpr int  TX  = (EPI == 0) ? 12 : ((EPI == 1) ? 8 : 4);
    constexpr int  TY  = (EPI == 1 || EPI == 2) ? 8 : 128;
    constexpr int  TZ  = (EPI == 1 || EPI == 2) ? 16 : 1;
    constexpr int  T   = TX * TY * TZ;

    constexpr int ASTG_B = 128 * 128;
    constexpr int BSTG_B = NT ? (128 * 128) : (64 * 272);
    extern __shared__ char smc[];
    char* Abuf = smc;
    char* Bbuf = smc + 3 * ASTG_B;

    int tid = threadIdx.x, lane = tid & 31, warp = tid >> 5;
    int wm = warp & 1, wn = warp >> 1;
    int bid = blockIdx.x;
    int GP = gridDim.x;
    int myN = (bid < T) ? ((T - 1 - bid) / GP + 1) : 0;
    int S = myN * KT;
    if (S == 0) return;

    float acc[4][8][4] = {};

    auto tileinfo = [&](int i, int& m0, int& n0, int& z) {
        int t = bid + i * GP;
        int x = t % TX;
        int y = (t / TX) % TY;
        z = t / (TX * TY);
        m0 = y * 128; n0 = x * 128;
    };

    auto load = [&](int s) {
        int i = s / KT;
        if (i < myN) {
            int m0, n0, z;
            tileinfo(i, m0, n0, z);
            int k0 = (s % KT) * 64;
            const __half* A;
            const __half* B;
            if constexpr (EPI == 0)      { A = g_xh;                        B = g_wqkvh; }
            else if constexpr (EPI == 1) { A = g_qh + (size_t)z * HW * C;   B = g_kh + (size_t)z * HW * C; }
            else if constexpr (EPI == 2) { A = g_sh + (size_t)z * HW * HW;  B = g_vh + (size_t)z * HW * C; }
            else                         { A = g_oh;                        B = g_wouth; }
            int st = s % 3;
            uint32_t Asm = smaddr(Abuf + st * ASTG_B);
            uint32_t Bsm = smaddr(Bbuf + st * BSTG_B);
#pragma unroll
            for (int q = 0; q < 8; q++) {
                int c = tid + q * 128;
                int r = c >> 3, ch = c & 7;
                CPA16(Asm + swz((uint32_t)(r * 128 + ch * 16)),
                      A + (size_t)(m0 + r) * LDA + k0 + ch * 8);
            }
            if constexpr (NT) {
#pragma unroll
                for (int q = 0; q < 8; q++) {
                    int c = tid + q * 128;
                    int r = c >> 3, ch = c & 7;
                    CPA16(Bsm + swz((uint32_t)(r * 128 + ch * 16)),
                          B + (size_t)(n0 + r) * LDB + k0 + ch * 8);
                }
            } else {
#pragma unroll
                for (int q = 0; q < 8; q++) {
                    int c = tid + q * 128;
                    int r = c >> 4, ch = c & 15;
                    CPA16(Bsm + (uint32_t)(r * 272 + ch * 16),
                          B + (size_t)(k0 + r) * LDB + n0 + ch * 8);
                }
            }
        }
        CPCOMMIT();
    };

    auto ldfrag = [&](int st, int ks, uint32_t a[4][4], uint32_t b[8][2]) {
        uint32_t Asm = smaddr(Abuf + st * ASTG_B);
        uint32_t Bsm = smaddr(Bbuf + st * BSTG_B);
        int colh = ks + ((lane >> 4) << 3);
#pragma unroll
        for (int mt = 0; mt < 4; mt++) {
            int r = wm * 64 + mt * 16 + (lane & 15);
            ldsm4(Asm + swz((uint32_t)(r * 128 + colh * 2)),
                  a[mt][0], a[mt][1], a[mt][2], a[mt][3]);
        }
        if constexpr (NT) {
#pragma unroll
            for (int ng = 0; ng < 4; ng++) {
                int r = wn * 64 + ng * 16 + (lane & 15);
                uint32_t r0, r1, r2, r3;
                ldsm4(Bsm + swz((uint32_t)(r * 128 + colh * 2)), r0, r1, r2, r3);
                b[2 * ng][0] = r0; b[2 * ng][1] = r2;
                b[2 * ng + 1][0] = r1; b[2 * ng + 1][1] = r3;
            }
        } else {
#pragma unroll
            for (int ng = 0; ng < 4; ng++) {
                int r = ks + (lane & 15);
                int col = wn * 64 + ng * 16 + ((lane >> 4) << 3);
                uint32_t r0, r1, r2, r3;
                ldsm4t(Bsm + (uint32_t)(r * 272 + col * 2), r0, r1, r2, r3);
                b[2 * ng][0] = r0; b[2 * ng][1] = r1;
                b[2 * ng + 1][0] = r2; b[2 * ng + 1][1] = r3;
            }
        }
    };

    auto mma_all = [&](uint32_t a[4][4], uint32_t b[8][2]) {
#pragma unroll
        for (int mt = 0; mt < 4; mt++)
#pragma unroll
            for (int nt = 0; nt < 8; nt++) mma16816(acc[mt][nt], a[mt], b[nt]);
    };

    auto epilogue = [&](int tile) {
        int m0, n0, z;
        tileinfo(tile, m0, n0, z);
#pragma unroll
        for (int mt = 0; mt < 4; mt++) {
#pragma unroll
            for (int nt = 0; nt < 8; nt++) {
                int r  = m0 + wm * 64 + mt * 16 + (lane >> 2);
                int nl = wn * 64 + nt * 8 + (lane & 3) * 2;
                float* v = acc[mt][nt];
                if constexpr (EPI == 0) {
                    int e = n0 >> 9;
                    __half* dst = (e == 0) ? g_qh : ((e == 1) ? g_kh : g_vh);
                    int ch = (n0 & 511) + nl;
                    float b0f = g_bqr[n0 + nl], b1f = g_bqr[n0 + nl + 1];
                    *(__half2*)&dst[(size_t)r * C + ch] =
                        __floats2half2_rn(v[0] + b0f, v[1] + b1f);
                    *(__half2*)&dst[(size_t)(r + 8) * C + ch] =
                        __floats2half2_rn(v[2] + b0f, v[3] + b1f);
                } else if constexpr (EPI == 1) {
                    size_t base = (size_t)z * HW * HW;
                    int cc = n0 + nl;
                    *(__half2*)&g_sh[base + (size_t)r * HW + cc] =
                        __floats2half2_rn(v[0], v[1]);
                    *(__half2*)&g_sh[base + (size_t)(r + 8) * HW + cc] =
                        __floats2half2_rn(v[2], v[3]);
                } else if constexpr (EPI == 2) {
                    size_t base = (size_t)z * HW * C;
                    int cc = n0 + nl;
                    *(__half2*)&g_oh[base + (size_t)r * C + cc] =
                        __floats2half2_rn(v[0], v[1]);
                    *(__half2*)&g_oh[base + (size_t)(r + 8) * C + cc] =
                        __floats2half2_rn(v[2], v[3]);
                } else {
                    int cc = n0 + nl;
                    outF[(size_t)r * C + cc]     = v[0] + bias[cc]     + resid[(size_t)r * C + cc];
                    outF[(size_t)r * C + cc + 1] = v[1] + bias[cc + 1] + resid[(size_t)r * C + cc + 1];
                    outF[(size_t)(r + 8) * C + cc]     = v[2] + bias[cc]     + resid[(size_t)(r + 8) * C + cc];
                    outF[(size_t)(r + 8) * C + cc + 1] = v[3] + bias[cc + 1] + resid[(size_t)(r + 8) * C + cc + 1];
                }
            }
        }
#pragma unroll
        for (int mt = 0; mt < 4; mt++)
#pragma unroll
            for (int nt = 0; nt < 8; nt++)
#pragma unroll
                for (int j = 0; j < 4; j++) acc[mt][nt][j] = 0.f;
    };

    // prologue: prime 3 loads, wait for the first, prefetch first frags
    load(0);
    load(1);
    load(2);
    CPWAIT2();
    __syncthreads();
    uint32_t aP[4][4], bP[8][2], aT[4][4], bT[8][2];
    ldfrag(0, 0, aP, bP);

    for (int s = 0; s < S; s++) {
        int st = s % 3;
        // frags (s, ks=0) already in aP/bP
        ldfrag(st, 16, aT, bT);
        mma_all(aP, bP);
        ldfrag(st, 32, aP, bP);
        mma_all(aT, bT);
        ldfrag(st, 48, aT, bT);
        mma_all(aP, bP);
        // all reads of stage st issued; ensure next stage resident, then flip
        CPWAIT1();                 // load(s+1) complete (load(s+2) may pend)
        __syncthreads();           // all warps done reading stage st
        ldfrag((s + 1) % 3, 0, aP, bP);   // prefetch next step's first frags
        load(s + 3);               // refill stage st (safe: post-barrier)
        mma_all(aT, bT);           // tail MMAs hide prefetch + issue
        if ((s + 1) % KT == 0) epilogue(s / KT);
    }
}

// ---------------------------------------------------------------------------
// fp16 in-place row softmax over 1024 cols: 128 thr, uint4/thread, 2 barriers
// ---------------------------------------------------------------------------
__global__ void softmax_h() {
    size_t row = blockIdx.x;
    uint4* p = (uint4*)(g_sh + row * HW);
    int tid = threadIdx.x, lane = tid & 31, warp = tid >> 5;
    uint4 raw = p[tid];
    __half2 h[4] = {*(__half2*)&raw.x, *(__half2*)&raw.y,
                    *(__half2*)&raw.z, *(__half2*)&raw.w};
    float2 f[4];
#pragma unroll
    for (int i = 0; i < 4; i++) f[i] = __half22float2(h[i]);

    float m = -1e30f;
#pragma unroll
    for (int i = 0; i < 4; i++) m = fmaxf(m, fmaxf(f[i].x, f[i].y));
#pragma unroll
    for (int o = 16; o; o >>= 1) m = fmaxf(m, __shfl_xor_sync(0xffffffffu, m, o));
    __shared__ float smax[4], ssum[4];
    if (lane == 0) smax[warp] = m;
    __syncthreads();
    m = fmaxf(fmaxf(smax[0], smax[1]), fmaxf(smax[2], smax[3]));

    float e[8];
    float s = 0.f;
#pragma unroll
    for (int i = 0; i < 4; i++) {
        e[2 * i]     = __expf(f[i].x - m);
        e[2 * i + 1] = __expf(f[i].y - m);
        s += e[2 * i] + e[2 * i + 1];
    }
#pragma unroll
    for (int o = 16; o; o >>= 1) s += __shfl_xor_sync(0xffffffffu, s, o);
    if (lane == 0) ssum[warp] = s;
    __syncthreads();
    float inv = 1.0f / (ssum[0] + ssum[1] + ssum[2] + ssum[3]);

    uint4 w;
    *(__half2*)&w.x = __floats2half2_rn(e[0] * inv, e[1] * inv);
    *(__half2*)&w.y = __floats2half2_rn(e[2] * inv, e[3] * inv);
    *(__half2*)&w.z = __floats2half2_rn(e[4] * inv, e[5] * inv);
    *(__half2*)&w.w = __floats2half2_rn(e[6] * inv, e[7] * inv);
    p[tid] = w;
}

// ---------------------------------------------------------------------------
extern "C" void kernel_launch(void* const* d_in, const int* in_sizes, int n_in,
                              void* d_out, int out_size) {
    (void)in_sizes; (void)n_in; (void)out_size;
    const float* inputs = (const float*)d_in[0];
    const float* gamma  = (const float*)d_in[1];
    const float* beta   = (const float*)d_in[2];
    const float* Wqkv   = (const float*)d_in[3];
    const float* bqkv   = (const float*)d_in[4];
    const float* Wout   = (const float*)d_in[5];
    const float* bout   = (const float*)d_in[6];
    float* out = (float*)d_out;

    const int smNT = 3 * (128 * 128 + 128 * 128);     // 98304
    const int smNN = 3 * (128 * 128 + 64 * 272);      // 101376
    cudaFuncSetAttribute(gemm_mma<0>, cudaFuncAttributeMaxDynamicSharedMemorySize, smNT);
    cudaFuncSetAttribute(gemm_mma<1>, cudaFuncAttributeMaxDynamicSharedMemorySize, smNT);
    cudaFuncSetAttribute(gemm_mma<2>, cudaFuncAttributeMaxDynamicSharedMemorySize, smNN);
    cudaFuncSetAttribute(gemm_mma<3>, cudaFuncAttributeMaxDynamicSharedMemorySize, smNN);

    conv_wqkv<<<(NQKV * C + 255) / 256, 256>>>(Wqkv, bqkv);
    f2h_wout<<<(C * C + 255) / 256, 256>>>(Wout);
    groupnorm_kernel<<<BNUM * G, 256>>>(inputs, gamma, beta);

    gemm_mma<0><<<NPERS, 128, smNT>>>(nullptr, nullptr, nullptr);
    gemm_mma<1><<<NPERS, 128, smNT>>>(nullptr, nullptr, nullptr);
    softmax_h<<<BNUM * HW, 128>>>();
    gemm_mma<2><<<NPERS, 128, smNN>>>(nullptr, nullptr, nullptr);
    gemm_mma<3><<<NPERS, 128, smNN>>>(bout, inputs, out);
}

// round 13
// speedup vs baseline: 1.0541x; 1.0164x over previous
#include <cuda_runtime.h>
#include <cuda_fp16.h>
#include <cstdint>
#include <cstddef>
#include <math.h>

#define BNUM 16
#define HW   1024
#define C    512
#define G    32
#define CG   16
#define NQKV 1536
#define MTOT (BNUM * HW)
#define SCALE 0.044194173824159216f   // 512^-0.5
#define NPERS 304                     // persistent CTAs (2/SM)

// fp16 scratch
__device__ __half g_xh[MTOT * C];
__device__ __half g_qh[MTOT * C];
__device__ __half g_kh[MTOT * C];
__device__ __half g_vh[MTOT * C];
__device__ __half g_sh[(size_t)BNUM * HW * HW];
__device__ __half g_oh[MTOT * C];
__device__ __half g_wqkvh[NQKV * C];   // permuted: [n'=e*512+ch][k], q-scale folded
__device__ __half g_wouth[C * C];
__device__ float  g_bqr[NQKV];         // permuted (scaled) qkv bias

// ---------------------------------------------------------------------------
// helpers
// ---------------------------------------------------------------------------
__device__ __forceinline__ uint32_t smaddr(const void* p) {
    return (uint32_t)__cvta_generic_to_shared(p);
}
__device__ __forceinline__ uint32_t swz(uint32_t off) {       // SW128 for 128B rows
    return off ^ ((off >> 3) & 0x70);
}
__device__ __forceinline__ void ldsm4(uint32_t a, uint32_t& r0, uint32_t& r1,
                                      uint32_t& r2, uint32_t& r3) {
    asm volatile("ldmatrix.sync.aligned.m8n8.x4.shared.b16 {%0,%1,%2,%3},[%4];"
                 : "=r"(r0), "=r"(r1), "=r"(r2), "=r"(r3) : "r"(a));
}
__device__ __forceinline__ void ldsm4t(uint32_t a, uint32_t& r0, uint32_t& r1,
                                       uint32_t& r2, uint32_t& r3) {
    asm volatile("ldmatrix.sync.aligned.m8n8.x4.trans.shared.b16 {%0,%1,%2,%3},[%4];"
                 : "=r"(r0), "=r"(r1), "=r"(r2), "=r"(r3) : "r"(a));
}
__device__ __forceinline__ void mma16816(float* d, const uint32_t* a, const uint32_t* b) {
    asm volatile(
        "mma.sync.aligned.m16n8k16.row.col.f32.f16.f16.f32 "
        "{%0,%1,%2,%3},{%4,%5,%6,%7},{%8,%9},{%0,%1,%2,%3};"
        : "+f"(d[0]), "+f"(d[1]), "+f"(d[2]), "+f"(d[3])
        : "r"(a[0]), "r"(a[1]), "r"(a[2]), "r"(a[3]), "r"(b[0]), "r"(b[1]));
}
#define CPA16(dst, src) \
    asm volatile("cp.async.cg.shared.global [%0],[%1],16;" ::"r"(dst), "l"(src))
#define CPCOMMIT() asm volatile("cp.async.commit_group;")
#define CPWAIT0()  asm volatile("cp.async.wait_group 0;")
#define CPWAIT1()  asm volatile("cp.async.wait_group 1;")

// ---------------------------------------------------------------------------
// weight converters (QKV permuted to [n'][k] + scale/bias folded)
// ---------------------------------------------------------------------------
__global__ void conv_wqkv(const float* __restrict__ W, const float* __restrict__ bq) {
    int idx = blockIdx.x * 256 + threadIdx.x;
    if (idx >= NQKV * C) return;
    int np = idx >> 9;          // n' = e*512 + ch
    int k  = idx & 511;
    int e  = np >> 9;
    int ch = np & 511;
    float s = (e == 0) ? SCALE : 1.0f;
    g_wqkvh[idx] = __float2half_rn(W[(size_t)k * NQKV + ch * 3 + e] * s);
    if (k == 0) g_bqr[np] = bq[ch * 3 + e] * s;
}
__global__ void f2h_wout(const float* __restrict__ s) {
    int i = blockIdx.x * 256 + threadIdx.x;
    if (i < C * C) g_wouth[i] = __float2half_rn(s[i]);
}

// ---------------------------------------------------------------------------
// GroupNorm -> fp16 g_xh (shuffle reduction, float2/half2)
// ---------------------------------------------------------------------------
__global__ void groupnorm_kernel(const float* __restrict__ in,
                                 const float* __restrict__ gamma,
                                 const float* __restrict__ beta) {
    int b = blockIdx.x >> 5;
    int g = blockIdx.x & 31;
    int tid = threadIdx.x, lane = tid & 31, warp = tid >> 5;
    const float* base = in + (size_t)b * HW * C + g * CG;
    float s = 0.f, ss = 0.f;
    for (int e = tid; e < HW * 8; e += 256) {       // float2 granules
        int pos = e >> 3, c2 = e & 7;
        float2 v = *(const float2*)(base + (size_t)pos * C + c2 * 2);
        s += v.x + v.y; ss += v.x * v.x + v.y * v.y;
    }
#pragma unroll
    for (int o = 16; o; o >>= 1) {
        s  += __shfl_xor_sync(0xffffffffu, s, o);
        ss += __shfl_xor_sync(0xffffffffu, ss, o);
    }
    __shared__ float sm_s[8], sm_ss[8];
    if (lane == 0) { sm_s[warp] = s; sm_ss[warp] = ss; }
    __syncthreads();
    float ts = 0.f, tss = 0.f;
#pragma unroll
    for (int i = 0; i < 8; i++) { ts += sm_s[i]; tss += sm_ss[i]; }
    const float invN = 1.0f / (HW * CG);
    float mean = ts * invN;
    float var  = tss * invN - mean * mean;
    float rstd = rsqrtf(var + 1e-3f);
    __half* outb = g_xh + (size_t)b * HW * C + g * CG;
    for (int e = tid; e < HW * 8; e += 256) {
        int pos = e >> 3, c2 = e & 7;
        float2 v = *(const float2*)(base + (size_t)pos * C + c2 * 2);
        float g0 = gamma[g * CG + c2 * 2], g1 = gamma[g * CG + c2 * 2 + 1];
        float b0 = beta[g * CG + c2 * 2],  b1 = beta[g * CG + c2 * 2 + 1];
        *(__half2*)(outb + (size_t)pos * C + c2 * 2) =
            __floats2half2_rn((v.x - mean) * rstd * g0 + b0,
                              (v.y - mean) * rstd * g1 + b1);
    }
}

// ---------------------------------------------------------------------------
// Persistent fp16 mma.sync GEMM (R9 structure): 128 thr (2x2 warps, 64x64
// warp tile), block tile 128x128, BK=64, 3-stage cp.async (distance 2),
// 1 barrier/step, frag ping-pong, 2 CTAs/SM.
// R13: scalar swizzle-base hoisting — every smem address is
// stageBase + perThreadConst + compile-time immediate (the SW128 XOR mask
// depends only on the 128-aligned row term). ldfrag(0/16) issued before
// cp.async issue so LDS latency hides the copy-issue slots.
// ---------------------------------------------------------------------------
template <int EPI>
__global__ void __launch_bounds__(128, 2)
gemm_mma(const float* __restrict__ bias,
         const float* __restrict__ resid,
         float* __restrict__ outF) {
    constexpr bool NT  = (EPI <= 1);
    constexpr int  K   = (EPI == 2) ? 1024 : 512;
    constexpr int  KT  = K / 64;
    constexpr int  LDA = (EPI == 2) ? 1024 : 512;
    constexpr int  LDB = 512;
    constexpr int  TX  = (EPI == 0) ? 12 : ((EPI == 1) ? 8 : 4);
    constexpr int  TY  = (EPI == 1 || EPI == 2) ? 8 : 128;
    constexpr int  TZ  = (EPI == 1 || EPI == 2) ? 16 : 1;
    constexpr int  T   = TX * TY * TZ;

    constexpr int ASTG_B = 128 * 128;
    constexpr int BSTG_B = NT ? (128 * 128) : (64 * 272);
    extern __shared__ char smc[];
    char* Abuf = smc;
    char* Bbuf = smc + 3 * ASTG_B;

    int tid = threadIdx.x, lane = tid & 31, warp = tid >> 5;
    int wm = warp & 1, wn = warp >> 1;
    int bid = blockIdx.x;
    int GP = gridDim.x;
    int myN = (bid < T) ? ((T - 1 - bid) / GP + 1) : 0;
    int S = myN * KT;
    if (S == 0) return;

    float acc[4][8][4] = {};

    // --- scalar per-thread address constants ---
    // ldfrag A: addr = stage + RA + ((cSel + 2*ks) ^ maskA) + mt*2048
    uint32_t cSel  = (uint32_t)((lane >> 4) << 4);
    uint32_t RA    = (uint32_t)((wm * 64 + (lane & 15)) * 128);
    uint32_t maskA = (RA >> 3) & 0x70;
    // ldfrag B (NT): addr = stage + RB + ((cSel + 2*ks) ^ maskB) + ng*2048
    uint32_t RB    = (uint32_t)((wn * 64 + (lane & 15)) * 128);
    uint32_t maskB = (RB >> 3) & 0x70;
    // ldfrag B (NN): addr = stage + BBnn + ks*272 + ng*32
    uint32_t BBnn  = (uint32_t)((lane & 15) * 272 + wn * 128 + ((lane >> 4) << 4));
    // cp.async A: smem = stage + cpA + q*2048 ; gmem = tilebase + gAo + q*16*LDA
    uint32_t rA    = (uint32_t)((tid >> 3) * 128);
    uint32_t cpA   = rA + (((uint32_t)((tid & 7) * 16)) ^ ((rA >> 3) & 0x70));
    size_t   gAo   = (size_t)(tid >> 3) * LDA + (tid & 7) * 8;
    // cp.async B
    uint32_t cpB;
    size_t   gBo;
    if constexpr (NT) { cpB = cpA; gBo = (size_t)(tid >> 3) * LDB + (tid & 7) * 8; }
    else { cpB = (uint32_t)((tid >> 4) * 272 + (tid & 15) * 16);
           gBo = (size_t)(tid >> 4) * LDB + (tid & 15) * 8; }

    auto tileinfo = [&](int i, int& m0, int& n0, int& z) {
        int t = bid + i * GP;
        int x = t % TX;
        int y = (t / TX) % TY;
        z = t / (TX * TY);
        m0 = y * 128; n0 = x * 128;
    };

    auto load = [&](int s) {
        int i = s / KT;
        if (i < myN) {
            int m0, n0, z;
            tileinfo(i, m0, n0, z);
            int k0 = (s % KT) * 64;
            const __half* A;
            const __half* B;
            if constexpr (EPI == 0)      { A = g_xh;                        B = g_wqkvh; }
            else if constexpr (EPI == 1) { A = g_qh + (size_t)z * HW * C;   B = g_kh + (size_t)z * HW * C; }
            else if constexpr (EPI == 2) { A = g_sh + (size_t)z * HW * HW;  B = g_vh + (size_t)z * HW * C; }
            else                         { A = g_oh;                        B = g_wouth; }
            int st = s % 3;
            uint32_t Asm = smaddr(Abuf + st * ASTG_B) + cpA;
            uint32_t Bsm = smaddr(Bbuf + st * BSTG_B) + cpB;
            const __half* Ab = A + (size_t)m0 * LDA + k0 + gAo;
            const __half* Bb = (NT ? (B + (size_t)n0 * LDB + k0)
                                   : (B + (size_t)k0 * LDB + n0)) + gBo;
#pragma unroll
            for (int q = 0; q < 8; q++)
                CPA16(Asm + q * 2048, Ab + (size_t)q * 16 * LDA);
            if constexpr (NT) {
#pragma unroll
                for (int q = 0; q < 8; q++)
                    CPA16(Bsm + q * 2048, Bb + (size_t)q * 16 * LDB);
            } else {
#pragma unroll
                for (int q = 0; q < 8; q++)
                    CPA16(Bsm + q * 2176, Bb + (size_t)q * 8 * LDB);
            }
        }
        CPCOMMIT();
    };

    auto ldfrag = [&](int st, int ks, uint32_t a[4][4], uint32_t b[8][2]) {
        uint32_t Asm = smaddr(Abuf + st * ASTG_B);
        uint32_t Bsm = smaddr(Bbuf + st * BSTG_B);
        uint32_t la = Asm + RA + ((cSel + (uint32_t)(2 * ks)) ^ maskA);
#pragma unroll
        for (int mt = 0; mt < 4; mt++)
            ldsm4(la + mt * 2048, a[mt][0], a[mt][1], a[mt][2], a[mt][3]);
        if constexpr (NT) {
            uint32_t lb = Bsm + RB + ((cSel + (uint32_t)(2 * ks)) ^ maskB);
#pragma unroll
            for (int ng = 0; ng < 4; ng++) {
                uint32_t r0, r1, r2, r3;
                ldsm4(lb + ng * 2048, r0, r1, r2, r3);
                b[2 * ng][0] = r0; b[2 * ng][1] = r2;
                b[2 * ng + 1][0] = r1; b[2 * ng + 1][1] = r3;
            }
        } else {
            uint32_t lb = Bsm + BBnn + (uint32_t)(ks * 272);
#pragma unroll
            for (int ng = 0; ng < 4; ng++) {
                uint32_t r0, r1, r2, r3;
                ldsm4t(lb + ng * 32, r0, r1, r2, r3);
                b[2 * ng][0] = r0; b[2 * ng][1] = r1;
                b[2 * ng + 1][0] = r2; b[2 * ng + 1][1] = r3;
            }
        }
    };

    auto mma_all = [&](uint32_t a[4][4], uint32_t b[8][2]) {
#pragma unroll
        for (int mt = 0; mt < 4; mt++)
#pragma unroll
            for (int nt = 0; nt < 8; nt++) mma16816(acc[mt][nt], a[mt], b[nt]);
    };

    auto epilogue = [&](int tile) {
        int m0, n0, z;
        tileinfo(tile, m0, n0, z);
#pragma unroll
        for (int mt = 0; mt < 4; mt++) {
#pragma unroll
            for (int nt = 0; nt < 8; nt++) {
                int r  = m0 + wm * 64 + mt * 16 + (lane >> 2);
                int nl = wn * 64 + nt * 8 + (lane & 3) * 2;
                float* v = acc[mt][nt];
                if constexpr (EPI == 0) {
                    int e = n0 >> 9;
                    __half* dst = (e == 0) ? g_qh : ((e == 1) ? g_kh : g_vh);
                    int ch = (n0 & 511) + nl;
                    float b0f = g_bqr[n0 + nl], b1f = g_bqr[n0 + nl + 1];
                    *(__half2*)&dst[(size_t)r * C + ch] =
                        __floats2half2_rn(v[0] + b0f, v[1] + b1f);
                    *(__half2*)&dst[(size_t)(r + 8) * C + ch] =
                        __floats2half2_rn(v[2] + b0f, v[3] + b1f);
                } else if constexpr (EPI == 1) {
                    size_t base = (size_t)z * HW * HW;
                    int cc = n0 + nl;
                    *(__half2*)&g_sh[base + (size_t)r * HW + cc] =
                        __floats2half2_rn(v[0], v[1]);
                    *(__half2*)&g_sh[base + (size_t)(r + 8) * HW + cc] =
                        __floats2half2_rn(v[2], v[3]);
                } else if constexpr (EPI == 2) {
                    size_t base = (size_t)z * HW * C;
                    int cc = n0 + nl;
                    *(__half2*)&g_oh[base + (size_t)r * C + cc] =
                        __floats2half2_rn(v[0], v[1]);
                    *(__half2*)&g_oh[base + (size_t)(r + 8) * C + cc] =
                        __floats2half2_rn(v[2], v[3]);
                } else {
                    int cc = n0 + nl;
                    outF[(size_t)r * C + cc]     = v[0] + bias[cc]     + resid[(size_t)r * C + cc];
                    outF[(size_t)r * C + cc + 1] = v[1] + bias[cc + 1] + resid[(size_t)r * C + cc + 1];
                    outF[(size_t)(r + 8) * C + cc]     = v[2] + bias[cc]     + resid[(size_t)(r + 8) * C + cc];
                    outF[(size_t)(r + 8) * C + cc + 1] = v[3] + bias[cc + 1] + resid[(size_t)(r + 8) * C + cc + 1];
                }
            }
        }
#pragma unroll
        for (int mt = 0; mt < 4; mt++)
#pragma unroll
            for (int nt = 0; nt < 8; nt++)
#pragma unroll
                for (int j = 0; j < 4; j++) acc[mt][nt][j] = 0.f;
    };

    load(0);
    load(1);

    for (int s = 0; s < S; s++) {
        if (s + 1 < S) { CPWAIT1(); } else { CPWAIT0(); }
        __syncthreads();
        int st = s % 3;
        uint32_t a0[4][4], b0[8][2], a1[4][4], b1[8][2];
        ldfrag(st, 0,  a0, b0);
        ldfrag(st, 16, a1, b1);
        load(s + 2);                 // cp.async issue hides in ldsm latency
        mma_all(a0, b0);
        ldfrag(st, 32, a0, b0);
        mma_all(a1, b1);
        ldfrag(st, 48, a1, b1);
        mma_all(a0, b0);
        mma_all(a1, b1);
        if ((s + 1) % KT == 0) epilogue(s / KT);
    }
}

// ---------------------------------------------------------------------------
// fp16 in-place row softmax over 1024 cols: 128 thr, uint4/thread, 2 barriers
// ---------------------------------------------------------------------------
__global__ void softmax_h() {
    size_t row = blockIdx.x;
    uint4* p = (uint4*)(g_sh + row * HW);
    int tid = threadIdx.x, lane = tid & 31, warp = tid >> 5;
    uint4 raw = p[tid];
    __half2 h[4] = {*(__half2*)&raw.x, *(__half2*)&raw.y,
                    *(__half2*)&raw.z, *(__half2*)&raw.w};
    float2 f[4];
#pragma unroll
    for (int i = 0; i < 4; i++) f[i] = __half22float2(h[i]);

    float m = -1e30f;
#pragma unroll
    for (int i = 0; i < 4; i++) m = fmaxf(m, fmaxf(f[i].x, f[i].y));
#pragma unroll
    for (int o = 16; o; o >>= 1) m = fmaxf(m, __shfl_xor_sync(0xffffffffu, m, o));
    __shared__ float smax[4], ssum[4];
    if (lane == 0) smax[warp] = m;
    __syncthreads();
    m = fmaxf(fmaxf(smax[0], smax[1]), fmaxf(smax[2], smax[3]));

    float e[8];
    float s = 0.f;
#pragma unroll
    for (int i = 0; i < 4; i++) {
        e[2 * i]     = __expf(f[i].x - m);
        e[2 * i + 1] = __expf(f[i].y - m);
        s += e[2 * i] + e[2 * i + 1];
    }
#pragma unroll
    for (int o = 16; o; o >>= 1) s += __shfl_xor_sync(0xffffffffu, s, o);
    if (lane == 0) ssum[warp] = s;
    __syncthreads();
    float inv = 1.0f / (ssum[0] + ssum[1] + ssum[2] + ssum[3]);

    uint4 w;
    *(__half2*)&w.x = __floats2half2_rn(e[0] * inv, e[1] * inv);
    *(__half2*)&w.y = __floats2half2_rn(e[2] * inv, e[3] * inv);
    *(__half2*)&w.z = __floats2half2_rn(e[4] * inv, e[5] * inv);
    *(__half2*)&w.w = __floats2half2_rn(e[6] * inv, e[7] * inv);
    p[tid] = w;
}

// ---------------------------------------------------------------------------
extern "C" void kernel_launch(void* const* d_in, const int* in_sizes, int n_in,
                              void* d_out, int out_size) {
    (void)in_sizes; (void)n_in; (void)out_size;
    const float* inputs = (const float*)d_in[0];
    const float* gamma  = (const float*)d_in[1];
    const float* beta   = (const float*)d_in[2];
    const float* Wqkv   = (const float*)d_in[3];
    const float* bqkv   = (const float*)d_in[4];
    const float* Wout   = (const float*)d_in[5];
    const float* bout   = (const float*)d_in[6];
    float* out = (float*)d_out;

    const int smNT = 3 * (128 * 128 + 128 * 128);     // 98304
    const int smNN = 3 * (128 * 128 + 64 * 272);      // 101376
    cudaFuncSetAttribute(gemm_mma<0>, cudaFuncAttributeMaxDynamicSharedMemorySize, smNT);
    cudaFuncSetAttribute(gemm_mma<1>, cudaFuncAttributeMaxDynamicSharedMemorySize, smNT);
    cudaFuncSetAttribute(gemm_mma<2>, cudaFuncAttributeMaxDynamicSharedMemorySize, smNN);
    cudaFuncSetAttribute(gemm_mma<3>, cudaFuncAttributeMaxDynamicSharedMemorySize, smNN);

    conv_wqkv<<<(NQKV * C + 255) / 256, 256>>>(Wqkv, bqkv);
    f2h_wout<<<(C * C + 255) / 256, 256>>>(Wout);
    groupnorm_kernel<<<BNUM * G, 256>>>(inputs, gamma, beta);

    gemm_mma<0><<<NPERS, 128, smNT>>>(nullptr, nullptr, nullptr);
    gemm_mma<1><<<NPERS, 128, smNT>>>(nullptr, nullptr, nullptr);
    softmax_h<<<BNUM * HW, 128>>>();
    gemm_mma<2><<<NPERS, 128, smNN>>>(nullptr, nullptr, nullptr);
    gemm_mma<3><<<NPERS, 128, smNN>>>(bout, inputs, out);
}

// round 14
// speedup vs baseline: 1.0942x; 1.0380x over previous
#include <cuda_runtime.h>
#include <cuda_fp16.h>
#include <cstdint>
#include <cstddef>
#include <math.h>

#define BNUM 16
#define HW   1024
#define C    512
#define G    32
#define CG   16
#define NQKV 1536
#define MTOT (BNUM * HW)
#define SCALE 0.044194173824159216f   // 512^-0.5
#define NPERS 304                     // persistent CTAs (2/SM)

// fp16 scratch
__device__ __half g_xh[MTOT * C];
__device__ __half g_qh[MTOT * C];
__device__ __half g_kh[MTOT * C];
__device__ __half g_vh[MTOT * C];
__device__ __half g_sh[(size_t)BNUM * HW * HW];
__device__ __half g_oh[MTOT * C];
__device__ __half g_wqkvh[NQKV * C];   // permuted: [n'=e*512+ch][k], q-scale folded
__device__ __half g_wouth[C * C];
__device__ float  g_bqr[NQKV];         // permuted (scaled) qkv bias

// ---------------------------------------------------------------------------
// helpers
// ---------------------------------------------------------------------------
__device__ __forceinline__ uint32_t smaddr(const void* p) {
    return (uint32_t)__cvta_generic_to_shared(p);
}
__device__ __forceinline__ uint32_t swz(uint32_t off) {       // SW128 for 128B rows
    return off ^ ((off >> 3) & 0x70);
}
__device__ __forceinline__ void ldsm4(uint32_t a, uint32_t& r0, uint32_t& r1,
                                      uint32_t& r2, uint32_t& r3) {
    asm volatile("ldmatrix.sync.aligned.m8n8.x4.shared.b16 {%0,%1,%2,%3},[%4];"
                 : "=r"(r0), "=r"(r1), "=r"(r2), "=r"(r3) : "r"(a));
}
__device__ __forceinline__ void ldsm4t(uint32_t a, uint32_t& r0, uint32_t& r1,
                                       uint32_t& r2, uint32_t& r3) {
    asm volatile("ldmatrix.sync.aligned.m8n8.x4.trans.shared.b16 {%0,%1,%2,%3},[%4];"
                 : "=r"(r0), "=r"(r1), "=r"(r2), "=r"(r3) : "r"(a));
}
__device__ __forceinline__ void mma16816(float* d, const uint32_t* a, const uint32_t* b) {
    asm volatile(
        "mma.sync.aligned.m16n8k16.row.col.f32.f16.f16.f32 "
        "{%0,%1,%2,%3},{%4,%5,%6,%7},{%8,%9},{%0,%1,%2,%3};"
        : "+f"(d[0]), "+f"(d[1]), "+f"(d[2]), "+f"(d[3])
        : "r"(a[0]), "r"(a[1]), "r"(a[2]), "r"(a[3]), "r"(b[0]), "r"(b[1]));
}
#define CPA16(dst, src) \
    asm volatile("cp.async.cg.shared.global [%0],[%1],16;" ::"r"(dst), "l"(src))
#define CPCOMMIT() asm volatile("cp.async.commit_group;")
#define CPWAIT0()  asm volatile("cp.async.wait_group 0;")
#define CPWAIT1()  asm volatile("cp.async.wait_group 1;")

// ---------------------------------------------------------------------------
// Fused prep: one launch does W_qkv permute/convert, W_out convert, GroupNorm.
// Block ranges:
//   [0, 512)            groupnorm, block = (b*32+g)
//   [512, 512+3072)     conv_wqkv
//   [3584, 3584+1024)   f2h_wout
// ---------------------------------------------------------------------------
__global__ void prep_kernel(const float* __restrict__ in,
                            const float* __restrict__ gamma,
                            const float* __restrict__ beta,
                            const float* __restrict__ Wq,
                            const float* __restrict__ bq,
                            const float* __restrict__ Wo) {
    int blk = blockIdx.x;
    int tid = threadIdx.x;

    if (blk >= 512) {
        if (blk < 3584) {
            // conv_wqkv
            int idx = (blk - 512) * 256 + tid;
            int np = idx >> 9;          // n' = e*512 + ch
            int k  = idx & 511;
            int e  = np >> 9;
            int ch = np & 511;
            float s = (e == 0) ? SCALE : 1.0f;
            g_wqkvh[idx] = __float2half_rn(Wq[(size_t)k * NQKV + ch * 3 + e] * s);
            if (k == 0) g_bqr[np] = bq[ch * 3 + e] * s;
        } else {
            // f2h_wout
            int idx = (blk - 3584) * 256 + tid;
            g_wouth[idx] = __float2half_rn(Wo[idx]);
        }
        return;
    }

    // groupnorm
    int b = blk >> 5;
    int g = blk & 31;
    int lane = tid & 31, warp = tid >> 5;
    const float* base = in + (size_t)b * HW * C + g * CG;
    float s = 0.f, ss = 0.f;
    for (int e = tid; e < HW * 8; e += 256) {       // float2 granules
        int pos = e >> 3, c2 = e & 7;
        float2 v = *(const float2*)(base + (size_t)pos * C + c2 * 2);
        s += v.x + v.y; ss += v.x * v.x + v.y * v.y;
    }
#pragma unroll
    for (int o = 16; o; o >>= 1) {
        s  += __shfl_xor_sync(0xffffffffu, s, o);
        ss += __shfl_xor_sync(0xffffffffu, ss, o);
    }
    __shared__ float sm_s[8], sm_ss[8];
    if (lane == 0) { sm_s[warp] = s; sm_ss[warp] = ss; }
    __syncthreads();
    float ts = 0.f, tss = 0.f;
#pragma unroll
    for (int i = 0; i < 8; i++) { ts += sm_s[i]; tss += sm_ss[i]; }
    const float invN = 1.0f / (HW * CG);
    float mean = ts * invN;
    float var  = tss * invN - mean * mean;
    float rstd = rsqrtf(var + 1e-3f);
    __half* outb = g_xh + (size_t)b * HW * C + g * CG;
    for (int e = tid; e < HW * 8; e += 256) {
        int pos = e >> 3, c2 = e & 7;
        float2 v = *(const float2*)(base + (size_t)pos * C + c2 * 2);
        float g0 = gamma[g * CG + c2 * 2], g1 = gamma[g * CG + c2 * 2 + 1];
        float b0 = beta[g * CG + c2 * 2],  b1 = beta[g * CG + c2 * 2 + 1];
        *(__half2*)(outb + (size_t)pos * C + c2 * 2) =
            __floats2half2_rn((v.x - mean) * rstd * g0 + b0,
                              (v.y - mean) * rstd * g1 + b1);
    }
}

// ---------------------------------------------------------------------------
// Persistent fp16 mma.sync GEMM (R9): 128 thr (2x2 warps, 64x64 warp tile),
// block tile 128x128, BK=64, 3-stage cp.async (distance 2), 1 barrier/step,
// frag ping-pong, SW128 swizzle, 2 CTAs/SM, NPERS persistent CTAs.
// ---------------------------------------------------------------------------
template <int EPI>
__global__ void __launch_bounds__(128, 2)
gemm_mma(const float* __restrict__ bias,
         const float* __restrict__ resid,
         float* __restrict__ outF) {
    constexpr bool NT  = (EPI <= 1);
    constexpr int  K   = (EPI == 2) ? 1024 : 512;
    constexpr int  KT  = K / 64;
    constexpr int  LDA = (EPI == 2) ? 1024 : 512;
    constexpr int  LDB = 512;
    constexpr int  TX  = (EPI == 0) ? 12 : ((EPI == 1) ? 8 : 4);
    constexpr int  TY  = (EPI == 1 || EPI == 2) ? 8 : 128;
    constexpr int  TZ  = (EPI == 1 || EPI == 2) ? 16 : 1;
    constexpr int  T   = TX * TY * TZ;

    constexpr int ASTG_B = 128 * 128;
    constexpr int BSTG_B = NT ? (128 * 128) : (64 * 272);
    extern __shared__ char smc[];
    char* Abuf = smc;
    char* Bbuf = smc + 3 * ASTG_B;

    int tid = threadIdx.x, lane = tid & 31, warp = tid >> 5;
    int wm = warp & 1, wn = warp >> 1;
    int bid = blockIdx.x;
    int GP = gridDim.x;
    int myN = (bid < T) ? ((T - 1 - bid) / GP + 1) : 0;
    int S = myN * KT;
    if (S == 0) return;

    float acc[4][8][4] = {};

    auto tileinfo = [&](int i, int& m0, int& n0, int& z) {
        int t = bid + i * GP;
        int x = t % TX;
        int y = (t / TX) % TY;
        z = t / (TX * TY);
        m0 = y * 128; n0 = x * 128;
    };

    auto load = [&](int s) {
        int i = s / KT;
        if (i < myN) {
            int m0, n0, z;
            tileinfo(i, m0, n0, z);
            int k0 = (s % KT) * 64;
            const __half* A;
            const __half* B;
            if constexpr (EPI == 0)      { A = g_xh;                        B = g_wqkvh; }
            else if constexpr (EPI == 1) { A = g_qh + (size_t)z * HW * C;   B = g_kh + (size_t)z * HW * C; }
            else if constexpr (EPI == 2) { A = g_sh + (size_t)z * HW * HW;  B = g_vh + (size_t)z * HW * C; }
            else                         { A = g_oh;                        B = g_wouth; }
            int st = s % 3;
            uint32_t Asm = smaddr(Abuf + st * ASTG_B);
            uint32_t Bsm = smaddr(Bbuf + st * BSTG_B);
#pragma unroll
            for (int q = 0; q < 8; q++) {
                int c = tid + q * 128;
                int r = c >> 3, ch = c & 7;
                CPA16(Asm + swz((uint32_t)(r * 128 + ch * 16)),
                      A + (size_t)(m0 + r) * LDA + k0 + ch * 8);
            }
            if constexpr (NT) {
#pragma unroll
                for (int q = 0; q < 8; q++) {
                    int c = tid + q * 128;
                    int r = c >> 3, ch = c & 7;
                    CPA16(Bsm + swz((uint32_t)(r * 128 + ch * 16)),
                          B + (size_t)(n0 + r) * LDB + k0 + ch * 8);
                }
            } else {
#pragma unroll
                for (int q = 0; q < 8; q++) {
                    int c = tid + q * 128;
                    int r = c >> 4, ch = c & 15;
                    CPA16(Bsm + (uint32_t)(r * 272 + ch * 16),
                          B + (size_t)(k0 + r) * LDB + n0 + ch * 8);
                }
            }
        }
        CPCOMMIT();
    };

    auto ldfrag = [&](int st, int ks, uint32_t a[4][4], uint32_t b[8][2]) {
        uint32_t Asm = smaddr(Abuf + st * ASTG_B);
        uint32_t Bsm = smaddr(Bbuf + st * BSTG_B);
        int colh = ks + ((lane >> 4) << 3);
#pragma unroll
        for (int mt = 0; mt < 4; mt++) {
            int r = wm * 64 + mt * 16 + (lane & 15);
            ldsm4(Asm + swz((uint32_t)(r * 128 + colh * 2)),
                  a[mt][0], a[mt][1], a[mt][2], a[mt][3]);
        }
        if constexpr (NT) {
#pragma unroll
            for (int ng = 0; ng < 4; ng++) {
                int r = wn * 64 + ng * 16 + (lane & 15);
                uint32_t r0, r1, r2, r3;
                ldsm4(Bsm + swz((uint32_t)(r * 128 + colh * 2)), r0, r1, r2, r3);
                b[2 * ng][0] = r0; b[2 * ng][1] = r2;
                b[2 * ng + 1][0] = r1; b[2 * ng + 1][1] = r3;
            }
        } else {
#pragma unroll
            for (int ng = 0; ng < 4; ng++) {
                int r = ks + (lane & 15);
                int col = wn * 64 + ng * 16 + ((lane >> 4) << 3);
                uint32_t r0, r1, r2, r3;
                ldsm4t(Bsm + (uint32_t)(r * 272 + col * 2), r0, r1, r2, r3);
                b[2 * ng][0] = r0; b[2 * ng][1] = r1;
                b[2 * ng + 1][0] = r2; b[2 * ng + 1][1] = r3;
            }
        }
    };

    auto mma_all = [&](uint32_t a[4][4], uint32_t b[8][2]) {
#pragma unroll
        for (int mt = 0; mt < 4; mt++)
#pragma unroll
            for (int nt = 0; nt < 8; nt++) mma16816(acc[mt][nt], a[mt], b[nt]);
    };

    auto epilogue = [&](int tile) {
        int m0, n0, z;
        tileinfo(tile, m0, n0, z);
#pragma unroll
        for (int mt = 0; mt < 4; mt++) {
#pragma unroll
            for (int nt = 0; nt < 8; nt++) {
                int r  = m0 + wm * 64 + mt * 16 + (lane >> 2);
                int nl = wn * 64 + nt * 8 + (lane & 3) * 2;
                float* v = acc[mt][nt];
                if constexpr (EPI == 0) {
                    int e = n0 >> 9;
                    __half* dst = (e == 0) ? g_qh : ((e == 1) ? g_kh : g_vh);
                    int ch = (n0 & 511) + nl;
                    float b0f = g_bqr[n0 + nl], b1f = g_bqr[n0 + nl + 1];
                    *(__half2*)&dst[(size_t)r * C + ch] =
                        __floats2half2_rn(v[0] + b0f, v[1] + b1f);
                    *(__half2*)&dst[(size_t)(r + 8) * C + ch] =
                        __floats2half2_rn(v[2] + b0f, v[3] + b1f);
                } else if constexpr (EPI == 1) {
                    size_t base = (size_t)z * HW * HW;
                    int cc = n0 + nl;
                    *(__half2*)&g_sh[base + (size_t)r * HW + cc] =
                        __floats2half2_rn(v[0], v[1]);
                    *(__half2*)&g_sh[base + (size_t)(r + 8) * HW + cc] =
                        __floats2half2_rn(v[2], v[3]);
                } else if constexpr (EPI == 2) {
                    size_t base = (size_t)z * HW * C;
                    int cc = n0 + nl;
                    *(__half2*)&g_oh[base + (size_t)r * C + cc] =
                        __floats2half2_rn(v[0], v[1]);
                    *(__half2*)&g_oh[base + (size_t)(r + 8) * C + cc] =
                        __floats2half2_rn(v[2], v[3]);
                } else {
                    int cc = n0 + nl;
                    outF[(size_t)r * C + cc]     = v[0] + bias[cc]     + resid[(size_t)r * C + cc];
                    outF[(size_t)r * C + cc + 1] = v[1] + bias[cc + 1] + resid[(size_t)r * C + cc + 1];
                    outF[(size_t)(r + 8) * C + cc]     = v[2] + bias[cc]     + resid[(size_t)(r + 8) * C + cc];
                    outF[(size_t)(r + 8) * C + cc + 1] = v[3] + bias[cc + 1] + resid[(size_t)(r + 8) * C + cc + 1];
                }
            }
        }
#pragma unroll
        for (int mt = 0; mt < 4; mt++)
#pragma unroll
            for (int nt = 0; nt < 8; nt++)
#pragma unroll
                for (int j = 0; j < 4; j++) acc[mt][nt][j] = 0.f;
    };

    load(0);
    load(1);

    for (int s = 0; s < S; s++) {
        if (s + 1 < S) { CPWAIT1(); } else { CPWAIT0(); }
        __syncthreads();
        load(s + 2);
        int st = s % 3;
        uint32_t a0[4][4], b0[8][2], a1[4][4], b1[8][2];
        ldfrag(st, 0,  a0, b0);
        ldfrag(st, 16, a1, b1);
        mma_all(a0, b0);
        ldfrag(st, 32, a0, b0);
        mma_all(a1, b1);
        ldfrag(st, 48, a1, b1);
        mma_all(a0, b0);
        mma_all(a1, b1);
        if ((s + 1) % KT == 0) epilogue(s / KT);
    }
}

// ---------------------------------------------------------------------------
// fp16 in-place row softmax over 1024 cols: 128 thr, uint4/thread, 2 barriers
// ---------------------------------------------------------------------------
__global__ void softmax_h() {
    size_t row = blockIdx.x;
    uint4* p = (uint4*)(g_sh + row * HW);
    int tid = threadIdx.x, lane = tid & 31, warp = tid >> 5;
    uint4 raw = p[tid];
    __half2 h[4] = {*(__half2*)&raw.x, *(__half2*)&raw.y,
                    *(__half2*)&raw.z, *(__half2*)&raw.w};
    float2 f[4];
#pragma unroll
    for (int i = 0; i < 4; i++) f[i] = __half22float2(h[i]);

    float m = -1e30f;
#pragma unroll
    for (int i = 0; i < 4; i++) m = fmaxf(m, fmaxf(f[i].x, f[i].y));
#pragma unroll
    for (int o = 16; o; o >>= 1) m = fmaxf(m, __shfl_xor_sync(0xffffffffu, m, o));
    __shared__ float smax[4], ssum[4];
    if (lane == 0) smax[warp] = m;
    __syncthreads();
    m = fmaxf(fmaxf(smax[0], smax[1]), fmaxf(smax[2], smax[3]));

    float e[8];
    float s = 0.f;
#pragma unroll
    for (int i = 0; i < 4; i++) {
        e[2 * i]     = __expf(f[i].x - m);
        e[2 * i + 1] = __expf(f[i].y - m);
        s += e[2 * i] + e[2 * i + 1];
    }
#pragma unroll
    for (int o = 16; o; o >>= 1) s += __shfl_xor_sync(0xffffffffu, s, o);
    if (lane == 0) ssum[warp] = s;
    __syncthreads();
    float inv = 1.0f / (ssum[0] + ssum[1] + ssum[2] + ssum[3]);

    uint4 w;
    *(__half2*)&w.x = __floats2half2_rn(e[0] * inv, e[1] * inv);
    *(__half2*)&w.y = __floats2half2_rn(e[2] * inv, e[3] * inv);
    *(__half2*)&w.z = __floats2half2_rn(e[4] * inv, e[5] * inv);
    *(__half2*)&w.w = __floats2half2_rn(e[6] * inv, e[7] * inv);
    p[tid] = w;
}

// ---------------------------------------------------------------------------
extern "C" void kernel_launch(void* const* d_in, const int* in_sizes, int n_in,
                              void* d_out, int out_size) {
    (void)in_sizes; (void)n_in; (void)out_size;
    const float* inputs = (const float*)d_in[0];
    const float* gamma  = (const float*)d_in[1];
    const float* beta   = (const float*)d_in[2];
    const float* Wqkv   = (const float*)d_in[3];
    const float* bqkv   = (const float*)d_in[4];
    const float* Wout   = (const float*)d_in[5];
    const float* bout   = (const float*)d_in[6];
    float* out = (float*)d_out;

    const int smNT = 3 * (128 * 128 + 128 * 128);     // 98304
    const int smNN = 3 * (128 * 128 + 64 * 272);      // 101376
    cudaFuncSetAttribute(gemm_mma<0>, cudaFuncAttributeMaxDynamicSharedMemorySize, smNT);
    cudaFuncSetAttribute(gemm_mma<1>, cudaFuncAttributeMaxDynamicSharedMemorySize, smNT);
    cudaFuncSetAttribute(gemm_mma<2>, cudaFuncAttributeMaxDynamicSharedMemorySize, smNN);
    cudaFuncSetAttribute(gemm_mma<3>, cudaFuncAttributeMaxDynamicSharedMemorySize, smNN);

    prep_kernel<<<4608, 256>>>(inputs, gamma, beta, Wqkv, bqkv, Wout);

    gemm_mma<0><<<NPERS, 128, smNT>>>(nullptr, nullptr, nullptr);
    gemm_mma<1><<<NPERS, 128, smNT>>>(nullptr, nullptr, nullptr);
    softmax_h<<<BNUM * HW, 128>>>();
    gemm_mma<2><<<NPERS, 128, smNN>>>(nullptr, nullptr, nullptr);
    gemm_mma<3><<<NPERS, 128, smNN>>>(bout, inputs, out);
}

// round 15
// speedup vs baseline: 1.1028x; 1.0078x over previous
#include <cuda_runtime.h>
#include <cuda_fp16.h>
#include <cstdint>
#include <cstddef>
#include <math.h>

#define BNUM 16
#define HW   1024
#define C    512
#define G    32
#define CG   16
#define NQKV 1536
#define MTOT (BNUM * HW)
#define SCALE 0.044194173824159216f   // 512^-0.5
#define NPERS 304                     // persistent CTAs (2/SM)

// fp16 scratch
__device__ __half g_xh[MTOT * C];
__device__ __half g_qh[MTOT * C];
__device__ __half g_kh[MTOT * C];
__device__ __half g_vh[MTOT * C];
__device__ __half g_sh[(size_t)BNUM * HW * HW];
__device__ __half g_oh[MTOT * C];
__device__ __half g_wqkvh[NQKV * C];   // permuted: [n'=e*512+ch][k], q-scale folded
__device__ __half g_wouth[C * C];
__device__ float  g_bqr[NQKV];         // permuted (scaled) qkv bias

// ---------------------------------------------------------------------------
// helpers
// ---------------------------------------------------------------------------
__device__ __forceinline__ uint32_t smaddr(const void* p) {
    return (uint32_t)__cvta_generic_to_shared(p);
}
__device__ __forceinline__ uint32_t swz(uint32_t off) {       // SW128 for 128B rows
    return off ^ ((off >> 3) & 0x70);
}
__device__ __forceinline__ void ldsm4(uint32_t a, uint32_t& r0, uint32_t& r1,
                                      uint32_t& r2, uint32_t& r3) {
    asm volatile("ldmatrix.sync.aligned.m8n8.x4.shared.b16 {%0,%1,%2,%3},[%4];"
                 : "=r"(r0), "=r"(r1), "=r"(r2), "=r"(r3) : "r"(a));
}
__device__ __forceinline__ void ldsm4t(uint32_t a, uint32_t& r0, uint32_t& r1,
                                       uint32_t& r2, uint32_t& r3) {
    asm volatile("ldmatrix.sync.aligned.m8n8.x4.trans.shared.b16 {%0,%1,%2,%3},[%4];"
                 : "=r"(r0), "=r"(r1), "=r"(r2), "=r"(r3) : "r"(a));
}
__device__ __forceinline__ void mma16816(float* d, const uint32_t* a, const uint32_t* b) {
    asm volatile(
        "mma.sync.aligned.m16n8k16.row.col.f32.f16.f16.f32 "
        "{%0,%1,%2,%3},{%4,%5,%6,%7},{%8,%9},{%0,%1,%2,%3};"
        : "+f"(d[0]), "+f"(d[1]), "+f"(d[2]), "+f"(d[3])
        : "r"(a[0]), "r"(a[1]), "r"(a[2]), "r"(a[3]), "r"(b[0]), "r"(b[1]));
}
__device__ __forceinline__ void mma16816h(uint32_t* d, const uint32_t* a, const uint32_t* b) {
    asm volatile(
        "mma.sync.aligned.m16n8k16.row.col.f16.f16.f16.f16 "
        "{%0,%1},{%2,%3,%4,%5},{%6,%7},{%0,%1};"
        : "+r"(d[0]), "+r"(d[1])
        : "r"(a[0]), "r"(a[1]), "r"(a[2]), "r"(a[3]), "r"(b[0]), "r"(b[1]));
}
#define CPA16(dst, src) \
    asm volatile("cp.async.cg.shared.global [%0],[%1],16;" ::"r"(dst), "l"(src))
#define CPCOMMIT() asm volatile("cp.async.commit_group;")
#define CPWAIT0()  asm volatile("cp.async.wait_group 0;")
#define CPWAIT1()  asm volatile("cp.async.wait_group 1;")

// ---------------------------------------------------------------------------
// Fused prep: W_qkv permute/convert, W_out convert, GroupNorm in one launch.
// ---------------------------------------------------------------------------
__global__ void prep_kernel(const float* __restrict__ in,
                            const float* __restrict__ gamma,
                            const float* __restrict__ beta,
                            const float* __restrict__ Wq,
                            const float* __restrict__ bq,
                            const float* __restrict__ Wo) {
    int blk = blockIdx.x;
    int tid = threadIdx.x;

    if (blk >= 512) {
        if (blk < 3584) {
            int idx = (blk - 512) * 256 + tid;
            int np = idx >> 9;
            int k  = idx & 511;
            int e  = np >> 9;
            int ch = np & 511;
            float s = (e == 0) ? SCALE : 1.0f;
            g_wqkvh[idx] = __float2half_rn(Wq[(size_t)k * NQKV + ch * 3 + e] * s);
            if (k == 0) g_bqr[np] = bq[ch * 3 + e] * s;
        } else {
            int idx = (blk - 3584) * 256 + tid;
            g_wouth[idx] = __float2half_rn(Wo[idx]);
        }
        return;
    }

    int b = blk >> 5;
    int g = blk & 31;
    int lane = tid & 31, warp = tid >> 5;
    const float* base = in + (size_t)b * HW * C + g * CG;
    float s = 0.f, ss = 0.f;
    for (int e = tid; e < HW * 8; e += 256) {
        int pos = e >> 3, c2 = e & 7;
        float2 v = *(const float2*)(base + (size_t)pos * C + c2 * 2);
        s += v.x + v.y; ss += v.x * v.x + v.y * v.y;
    }
#pragma unroll
    for (int o = 16; o; o >>= 1) {
        s  += __shfl_xor_sync(0xffffffffu, s, o);
        ss += __shfl_xor_sync(0xffffffffu, ss, o);
    }
    __shared__ float sm_s[8], sm_ss[8];
    if (lane == 0) { sm_s[warp] = s; sm_ss[warp] = ss; }
    __syncthreads();
    float ts = 0.f, tss = 0.f;
#pragma unroll
    for (int i = 0; i < 8; i++) { ts += sm_s[i]; tss += sm_ss[i]; }
    const float invN = 1.0f / (HW * CG);
    float mean = ts * invN;
    float var  = tss * invN - mean * mean;
    float rstd = rsqrtf(var + 1e-3f);
    __half* outb = g_xh + (size_t)b * HW * C + g * CG;
    for (int e = tid; e < HW * 8; e += 256) {
        int pos = e >> 3, c2 = e & 7;
        float2 v = *(const float2*)(base + (size_t)pos * C + c2 * 2);
        float g0 = gamma[g * CG + c2 * 2], g1 = gamma[g * CG + c2 * 2 + 1];
        float b0 = beta[g * CG + c2 * 2],  b1 = beta[g * CG + c2 * 2 + 1];
        *(__half2*)(outb + (size_t)pos * C + c2 * 2) =
            __floats2half2_rn((v.x - mean) * rstd * g0 + b0,
                              (v.y - mean) * rstd * g1 + b1);
    }
}

// ---------------------------------------------------------------------------
// Persistent fp16 mma.sync GEMM (R9 structure). EPI 1 uses fp16 accumulators
// (precision budget: ~1e-2 abs on logits -> ~3e-4 final rel_err after
// softmax + residual dilution). Others keep fp32 accumulate.
// ---------------------------------------------------------------------------
template <int EPI>
__global__ void __launch_bounds__(128, 2)
gemm_mma(const float* __restrict__ bias,
         const float* __restrict__ resid,
         float* __restrict__ outF) {
    constexpr bool NT  = (EPI <= 1);
    constexpr bool HACC = (EPI == 1);
    constexpr int  K   = (EPI == 2) ? 1024 : 512;
    constexpr int  KT  = K / 64;
    constexpr int  LDA = (EPI == 2) ? 1024 : 512;
    constexpr int  LDB = 512;
    constexpr int  TX  = (EPI == 0) ? 12 : ((EPI == 1) ? 8 : 4);
    constexpr int  TY  = (EPI == 1 || EPI == 2) ? 8 : 128;
    constexpr int  TZ  = (EPI == 1 || EPI == 2) ? 16 : 1;
    constexpr int  T   = TX * TY * TZ;

    constexpr int ASTG_B = 128 * 128;
    constexpr int BSTG_B = NT ? (128 * 128) : (64 * 272);
    extern __shared__ char smc[];
    char* Abuf = smc;
    char* Bbuf = smc + 3 * ASTG_B;

    int tid = threadIdx.x, lane = tid & 31, warp = tid >> 5;
    int wm = warp & 1, wn = warp >> 1;
    int bid = blockIdx.x;
    int GP = gridDim.x;
    int myN = (bid < T) ? ((T - 1 - bid) / GP + 1) : 0;
    int S = myN * KT;
    if (S == 0) return;

    float    acc[HACC ? 1 : 4][8][4] = {};
    uint32_t acch[HACC ? 4 : 1][8][2] = {};

    auto tileinfo = [&](int i, int& m0, int& n0, int& z) {
        int t = bid + i * GP;
        int x = t % TX;
        int y = (t / TX) % TY;
        z = t / (TX * TY);
        m0 = y * 128; n0 = x * 128;
    };

    auto load = [&](int s) {
        int i = s / KT;
        if (i < myN) {
            int m0, n0, z;
            tileinfo(i, m0, n0, z);
            int k0 = (s % KT) * 64;
            const __half* A;
            const __half* B;
            if constexpr (EPI == 0)      { A = g_xh;                        B = g_wqkvh; }
            else if constexpr (EPI == 1) { A = g_qh + (size_t)z * HW * C;   B = g_kh + (size_t)z * HW * C; }
            else if constexpr (EPI == 2) { A = g_sh + (size_t)z * HW * HW;  B = g_vh + (size_t)z * HW * C; }
            else                         { A = g_oh;                        B = g_wouth; }
            int st = s % 3;
            uint32_t Asm = smaddr(Abuf + st * ASTG_B);
            uint32_t Bsm = smaddr(Bbuf + st * BSTG_B);
#pragma unroll
            for (int q = 0; q < 8; q++) {
                int c = tid + q * 128;
                int r = c >> 3, ch = c & 7;
                CPA16(Asm + swz((uint32_t)(r * 128 + ch * 16)),
                      A + (size_t)(m0 + r) * LDA + k0 + ch * 8);
            }
            if constexpr (NT) {
#pragma unroll
                for (int q = 0; q < 8; q++) {
                    int c = tid + q * 128;
                    int r = c >> 3, ch = c & 7;
                    CPA16(Bsm + swz((uint32_t)(r * 128 + ch * 16)),
                          B + (size_t)(n0 + r) * LDB + k0 + ch * 8);
                }
            } else {
#pragma unroll
                for (int q = 0; q < 8; q++) {
                    int c = tid + q * 128;
                    int r = c >> 4, ch = c & 15;
                    CPA16(Bsm + (uint32_t)(r * 272 + ch * 16),
                          B + (size_t)(k0 + r) * LDB + n0 + ch * 8);
                }
            }
        }
        CPCOMMIT();
    };

    auto ldfrag = [&](int st, int ks, uint32_t a[4][4], uint32_t b[8][2]) {
        uint32_t Asm = smaddr(Abuf + st * ASTG_B);
        uint32_t Bsm = smaddr(Bbuf + st * BSTG_B);
        int colh = ks + ((lane >> 4) << 3);
#pragma unroll
        for (int mt = 0; mt < 4; mt++) {
            int r = wm * 64 + mt * 16 + (lane & 15);
            ldsm4(Asm + swz((uint32_t)(r * 128 + colh * 2)),
                  a[mt][0], a[mt][1], a[mt][2], a[mt][3]);
        }
        if constexpr (NT) {
#pragma unroll
            for (int ng = 0; ng < 4; ng++) {
                int r = wn * 64 + ng * 16 + (lane & 15);
                uint32_t r0, r1, r2, r3;
                ldsm4(Bsm + swz((uint32_t)(r * 128 + colh * 2)), r0, r1, r2, r3);
                b[2 * ng][0] = r0; b[2 * ng][1] = r2;
                b[2 * ng + 1][0] = r1; b[2 * ng + 1][1] = r3;
            }
        } else {
#pragma unroll
            for (int ng = 0; ng < 4; ng++) {
                int r = ks + (lane & 15);
                int col = wn * 64 + ng * 16 + ((lane >> 4) << 3);
                uint32_t r0, r1, r2, r3;
                ldsm4t(Bsm + (uint32_t)(r * 272 + col * 2), r0, r1, r2, r3);
                b[2 * ng][0] = r0; b[2 * ng][1] = r1;
                b[2 * ng + 1][0] = r2; b[2 * ng + 1][1] = r3;
            }
        }
    };

    auto mma_all = [&](uint32_t a[4][4], uint32_t b[8][2]) {
#pragma unroll
        for (int mt = 0; mt < 4; mt++)
#pragma unroll
            for (int nt = 0; nt < 8; nt++) {
                if constexpr (HACC) mma16816h(acch[mt][nt], a[mt], b[nt]);
                else                mma16816(acc[mt][nt], a[mt], b[nt]);
            }
    };

    auto epilogue = [&](int tile) {
        int m0, n0, z;
        tileinfo(tile, m0, n0, z);
#pragma unroll
        for (int mt = 0; mt < 4; mt++) {
#pragma unroll
            for (int nt = 0; nt < 8; nt++) {
                int r  = m0 + wm * 64 + mt * 16 + (lane >> 2);
                int nl = wn * 64 + nt * 8 + (lane & 3) * 2;
                if constexpr (EPI == 1) {
                    size_t base = (size_t)z * HW * HW;
                    int cc = n0 + nl;
                    *(uint32_t*)&g_sh[base + (size_t)r * HW + cc] = acch[mt][nt][0];
                    *(uint32_t*)&g_sh[base + (size_t)(r + 8) * HW + cc] = acch[mt][nt][1];
                    acch[mt][nt][0] = 0u; acch[mt][nt][1] = 0u;
                } else {
                    float* v = acc[mt][nt];
                    if constexpr (EPI == 0) {
                        int e = n0 >> 9;
                        __half* dst = (e == 0) ? g_qh : ((e == 1) ? g_kh : g_vh);
                        int ch = (n0 & 511) + nl;
                        float b0f = g_bqr[n0 + nl], b1f = g_bqr[n0 + nl + 1];
                        *(__half2*)&dst[(size_t)r * C + ch] =
                            __floats2half2_rn(v[0] + b0f, v[1] + b1f);
                        *(__half2*)&dst[(size_t)(r + 8) * C + ch] =
                            __floats2half2_rn(v[2] + b0f, v[3] + b1f);
                    } else if constexpr (EPI == 2) {
                        size_t base = (size_t)z * HW * C;
                        int cc = n0 + nl;
                        *(__half2*)&g_oh[base + (size_t)r * C + cc] =
                            __floats2half2_rn(v[0], v[1]);
                        *(__half2*)&g_oh[base + (size_t)(r + 8) * C + cc] =
                            __floats2half2_rn(v[2], v[3]);
                    } else {
                        int cc = n0 + nl;
                        outF[(size_t)r * C + cc]     = v[0] + bias[cc]     + resid[(size_t)r * C + cc];
                        outF[(size_t)r * C + cc + 1] = v[1] + bias[cc + 1] + resid[(size_t)r * C + cc + 1];
                        outF[(size_t)(r + 8) * C + cc]     = v[2] + bias[cc]     + resid[(size_t)(r + 8) * C + cc];
                        outF[(size_t)(r + 8) * C + cc + 1] = v[3] + bias[cc + 1] + resid[(size_t)(r + 8) * C + cc + 1];
                    }
                    v[0] = v[1] = v[2] = v[3] = 0.f;
                }
            }
        }
    };

    load(0);
    load(1);

    for (int s = 0; s < S; s++) {
        if (s + 1 < S) { CPWAIT1(); } else { CPWAIT0(); }
        __syncthreads();
        load(s + 2);
        int st = s % 3;
        uint32_t a0[4][4], b0[8][2], a1[4][4], b1[8][2];
        ldfrag(st, 0,  a0, b0);
        ldfrag(st, 16, a1, b1);
        mma_all(a0, b0);
        ldfrag(st, 32, a0, b0);
        mma_all(a1, b1);
        ldfrag(st, 48, a1, b1);
        mma_all(a0, b0);
        mma_all(a1, b1);
        if ((s + 1) % KT == 0) epilogue(s / KT);
    }
}

// ---------------------------------------------------------------------------
// fp16 in-place row softmax over 1024 cols: 128 thr, uint4/thread, 2 barriers
// ---------------------------------------------------------------------------
__global__ void softmax_h() {
    size_t row = blockIdx.x;
    uint4* p = (uint4*)(g_sh + row * HW);
    int tid = threadIdx.x, lane = tid & 31, warp = tid >> 5;
    uint4 raw = p[tid];
    __half2 h[4] = {*(__half2*)&raw.x, *(__half2*)&raw.y,
                    *(__half2*)&raw.z, *(__half2*)&raw.w};
    float2 f[4];
#pragma unroll
    for (int i = 0; i < 4; i++) f[i] = __half22float2(h[i]);

    float m = -1e30f;
#pragma unroll
    for (int i = 0; i < 4; i++) m = fmaxf(m, fmaxf(f[i].x, f[i].y));
#pragma unroll
    for (int o = 16; o; o >>= 1) m = fmaxf(m, __shfl_xor_sync(0xffffffffu, m, o));
    __shared__ float smax[4], ssum[4];
    if (lane == 0) smax[warp] = m;
    __syncthreads();
    m = fmaxf(fmaxf(smax[0], smax[1]), fmaxf(smax[2], smax[3]));

    float e[8];
    float s = 0.f;
#pragma unroll
    for (int i = 0; i < 4; i++) {
        e[2 * i]     = __expf(f[i].x - m);
        e[2 * i + 1] = __expf(f[i].y - m);
        s += e[2 * i] + e[2 * i + 1];
    }
#pragma unroll
    for (int o = 16; o; o >>= 1) s += __shfl_xor_sync(0xffffffffu, s, o);
    if (lane == 0) ssum[warp] = s;
    __syncthreads();
    float inv = 1.0f / (ssum[0] + ssum[1] + ssum[2] + ssum[3]);

    uint4 w;
    *(__half2*)&w.x = __floats2half2_rn(e[0] * inv, e[1] * inv);
    *(__half2*)&w.y = __floats2half2_rn(e[2] * inv, e[3] * inv);
    *(__half2*)&w.z = __floats2half2_rn(e[4] * inv, e[5] * inv);
    *(__half2*)&w.w = __floats2half2_rn(e[6] * inv, e[7] * inv);
    p[tid] = w;
}

// ---------------------------------------------------------------------------
extern "C" void kernel_launch(void* const* d_in, const int* in_sizes, int n_in,
                              void* d_out, int out_size) {
    (void)in_sizes; (void)n_in; (void)out_size;
    const float* inputs = (const float*)d_in[0];
    const float* gamma  = (const float*)d_in[1];
    const float* beta   = (const float*)d_in[2];
    const float* Wqkv   = (const float*)d_in[3];
    const float* bqkv   = (const float*)d_in[4];
    const float* Wout   = (const float*)d_in[5];
    const float* bout   = (const float*)d_in[6];
    float* out = (float*)d_out;

    const int smNT = 3 * (128 * 128 + 128 * 128);     // 98304
    const int smNN = 3 * (128 * 128 + 64 * 272);      // 101376
    cudaFuncSetAttribute(gemm_mma<0>, cudaFuncAttributeMaxDynamicSharedMemorySize, smNT);
    cudaFuncSetAttribute(gemm_mma<1>, cudaFuncAttributeMaxDynamicSharedMemorySize, smNT);
    cudaFuncSetAttribute(gemm_mma<2>, cudaFuncAttributeMaxDynamicSharedMemorySize, smNN);
    cudaFuncSetAttribute(gemm_mma<3>, cudaFuncAttributeMaxDynamicSharedMemorySize, smNN);

    prep_kernel<<<4608, 256>>>(inputs, gamma, beta, Wqkv, bqkv, Wout);

    gemm_mma<0><<<NPERS, 128, smNT>>>(nullptr, nullptr, nullptr);
    gemm_mma<1><<<NPERS, 128, smNT>>>(nullptr, nullptr, nullptr);
    softmax_h<<<BNUM * HW, 128>>>();
    gemm_mma<2><<<NPERS, 128, smNN>>>(nullptr, nullptr, nullptr);
    gemm_mma<3><<<NPERS, 128, smNN>>>(bout, inputs, out);
}